// round 1
// baseline (speedup 1.0000x reference)
#include <cuda_runtime.h>
#include <math.h>

// ---------------- problem constants ----------------
#define B_   8
#define N_   256
#define C_   3072
#define H_   8
#define HD_  384          // head dim
#define FF_  12288
#define P_   32           // patch spatial
#define NC_  (N_*C_)      // 786432 per-batch elems
#define BH_  (B_*H_)      // 64
#define QKV_SZ   (B_*N_*C_)          // 6291456
#define ATT_SZ   (B_*H_*N_*N_)       // 4194304
#define HBUF_SZ  (B_*N_*FF_)         // 25165824

// ---------------- device scratch ----------------
__device__ float g_q[QKV_SZ];
__device__ float g_k[QKV_SZ];
__device__ float g_v[QKV_SZ];
__device__ float g_attn[ATT_SZ];
__device__ float g_attn2[ATT_SZ];
__device__ float g_ctx[QKV_SZ];
__device__ float g_y1[QKV_SZ];
__device__ float g_yn[QKV_SZ];
__device__ float g_y2[QKV_SZ];
__device__ float g_h[HBUF_SZ];
__device__ float g_stats[B_*2];

// ---------------- helpers ----------------
__device__ __forceinline__ float gelu_exact(float x) {
    return 0.5f * x * (1.0f + erff(x * 0.70710678118654752f));
}

// ---------------- conv QKV ----------------
// one block per patch (B*N = 2048), 256 threads
__global__ void conv_qkv_kernel(const float* __restrict__ x,
                                const float* __restrict__ qw,
                                const float* __restrict__ kw,
                                const float* __restrict__ vw)
{
    __shared__ float sp[3][P_+2][P_+2];   // zero-padded patch
    __shared__ float swq[81], swk[81], swv[81];
    int tid = threadIdx.x;
    int patch = blockIdx.x;
    int b = patch >> 8;
    int n = patch & 255;
    const float* xp = x + (long)patch * C_;

    if (tid < 81) { swq[tid] = qw[tid]; swk[tid] = kw[tid]; swv[tid] = vw[tid]; }
    // zero whole padded patch
    for (int i = tid; i < 3*(P_+2)*(P_+2); i += 256)
        ((float*)sp)[i] = 0.0f;
    __syncthreads();
    // fill interior
    for (int i = tid; i < C_; i += 256) {
        int ch = i >> 10;        // /1024
        int s  = i & 1023;
        int yy = s >> 5, xx = s & 31;
        sp[ch][yy+1][xx+1] = xp[i];
    }
    __syncthreads();

    for (int pos = tid; pos < 1024; pos += 256) {
        int yy = pos >> 5, xx = pos & 31;
        float aq[3] = {0,0,0}, ak[3] = {0,0,0}, av[3] = {0,0,0};
        #pragma unroll
        for (int i = 0; i < 3; i++)
            #pragma unroll
            for (int dy = 0; dy < 3; dy++)
                #pragma unroll
                for (int dx = 0; dx < 3; dx++) {
                    float val = sp[i][yy+dy][xx+dx];
                    int wi = i*9 + dy*3 + dx;
                    #pragma unroll
                    for (int o = 0; o < 3; o++) {
                        aq[o] = fmaf(val, swq[o*27 + wi], aq[o]);
                        ak[o] = fmaf(val, swk[o*27 + wi], ak[o]);
                        av[o] = fmaf(val, swv[o*27 + wi], av[o]);
                    }
                }
        #pragma unroll
        for (int o = 0; o < 3; o++) {
            int c = o*1024 + pos;
            int h = c / HD_;
            int d = c - h*HD_;
            long dst = (((long)(b*H_ + h))*N_ + n)*HD_ + d;
            g_q[dst] = aq[o];
            g_k[dst] = ak[o];
            g_v[dst] = av[o];
        }
    }
}

// ---------------- generic 128x128 fp32 GEMM ----------------
// EPI: 0 plain, 1 +bias, 2 +bias+gelu, 3 +bias+residual
template<bool TRANSB, int EPI>
__global__ void sgemm128(const float* __restrict__ A, const float* __restrict__ Bm,
                         float* __restrict__ C,
                         int M, int N, int K, int lda, int ldb, int ldc,
                         long sA, long sB, int zdiv, long sC1, long sC2,
                         const float* __restrict__ bias,
                         const float* __restrict__ resid)
{
    const int BK = 8;
    __shared__ float As[BK][128];
    __shared__ float Bs[BK][128];
    int z = blockIdx.z;
    const float* Ab = A + (long)z * sA;
    const float* Bb = Bm + (long)z * sB;
    long coff = (long)(z / zdiv) * sC1 + (long)(z % zdiv) * sC2;
    float* Cb = C + coff;

    int tid = threadIdx.x;
    int rowBlk = blockIdx.y * 128;
    int colBlk = blockIdx.x * 128;

    float acc[8][8];
    #pragma unroll
    for (int i = 0; i < 8; i++)
        #pragma unroll
        for (int j = 0; j < 8; j++) acc[i][j] = 0.0f;

    int tx = tid & 15, ty = tid >> 4;
    int arow = tid >> 1;           // 0..127
    int acol = (tid & 1) * 4;      // 0/4
    int brow = tid >> 5;           // 0..7   (NN)
    int bcol = (tid & 31) * 4;     //        (NN)
    int bn   = tid >> 1;           // 0..127 (NT)
    int bk   = (tid & 1) * 4;      //        (NT)

    for (int kt = 0; kt < K; kt += BK) {
        float4 av = *(const float4*)(Ab + (long)(rowBlk + arow) * lda + kt + acol);
        As[acol+0][arow] = av.x;
        As[acol+1][arow] = av.y;
        As[acol+2][arow] = av.z;
        As[acol+3][arow] = av.w;
        if (TRANSB) {
            float4 bv = *(const float4*)(Bb + (long)(colBlk + bn) * ldb + kt + bk);
            Bs[bk+0][bn] = bv.x;
            Bs[bk+1][bn] = bv.y;
            Bs[bk+2][bn] = bv.z;
            Bs[bk+3][bn] = bv.w;
        } else {
            float4 bv = *(const float4*)(Bb + (long)(kt + brow) * ldb + colBlk + bcol);
            *(float4*)&Bs[brow][bcol] = bv;
        }
        __syncthreads();
        #pragma unroll
        for (int kk = 0; kk < BK; kk++) {
            float4 a0 = *(const float4*)&As[kk][ty*8];
            float4 a1 = *(const float4*)&As[kk][ty*8+4];
            float4 b0 = *(const float4*)&Bs[kk][tx*8];
            float4 b1 = *(const float4*)&Bs[kk][tx*8+4];
            float a[8] = {a0.x,a0.y,a0.z,a0.w,a1.x,a1.y,a1.z,a1.w};
            float b[8] = {b0.x,b0.y,b0.z,b0.w,b1.x,b1.y,b1.z,b1.w};
            #pragma unroll
            for (int i = 0; i < 8; i++)
                #pragma unroll
                for (int j = 0; j < 8; j++)
                    acc[i][j] = fmaf(a[i], b[j], acc[i][j]);
        }
        __syncthreads();
    }

    #pragma unroll
    for (int i = 0; i < 8; i++) {
        int r = rowBlk + ty*8 + i;
        #pragma unroll
        for (int j = 0; j < 8; j++) {
            int c = colBlk + tx*8 + j;
            float v = acc[i][j];
            if (EPI >= 1) v += bias[c];
            if (EPI == 2) v = gelu_exact(v);
            if (EPI == 3) v += resid[coff + (long)r*ldc + c];
            Cb[(long)r*ldc + c] = v;
        }
    }
}

// ---------------- softmax over rows of length 256 ----------------
__global__ void softmax256(float* __restrict__ attn, float scale)
{
    __shared__ float red[8];
    long row = blockIdx.x;
    float* p = attn + row * 256;
    int tid = threadIdx.x;
    float v = p[tid] * scale;
    float m = v;
    #pragma unroll
    for (int o = 16; o > 0; o >>= 1) m = fmaxf(m, __shfl_xor_sync(0xffffffffu, m, o));
    if ((tid & 31) == 0) red[tid >> 5] = m;
    __syncthreads();
    float bm = red[0];
    #pragma unroll
    for (int i = 1; i < 8; i++) bm = fmaxf(bm, red[i]);
    float e = __expf(v - bm);
    float s = e;
    #pragma unroll
    for (int o = 16; o > 0; o >>= 1) s += __shfl_xor_sync(0xffffffffu, s, o);
    __syncthreads();
    if ((tid & 31) == 0) red[tid >> 5] = s;
    __syncthreads();
    float bs = 0.0f;
    #pragma unroll
    for (int i = 0; i < 8; i++) bs += red[i];
    p[tid] = e / bs;
}

// ---------------- re-attention (head mix + BN) ----------------
__global__ void reatten_kernel(const float* __restrict__ w,  const float* __restrict__ rb,
                               const float* __restrict__ g,  const float* __restrict__ bta,
                               const float* __restrict__ mean, const float* __restrict__ var)
{
    __shared__ float sw[64], sscale[8], sshift[8];
    int tid = threadIdx.x;
    if (tid < 64) sw[tid] = w[tid];
    if (tid < 8) {
        float inv = rsqrtf(var[tid] + 1e-5f);
        float gi = g[tid] * inv;
        sscale[tid] = gi;
        sshift[tid] = bta[tid] + (rb[tid] - mean[tid]) * gi;
    }
    __syncthreads();
    long idx = (long)blockIdx.x * blockDim.x + tid;     // over B * (N*N)
    int b  = (int)(idx >> 16);
    int nm = (int)(idx & 65535);
    const float* base = g_attn + ((long)b * H_) * 65536 + nm;
    float in[8];
    #pragma unroll
    for (int i = 0; i < 8; i++) in[i] = base[(long)i * 65536];
    float* obase = g_attn2 + ((long)b * H_) * 65536 + nm;
    #pragma unroll
    for (int o = 0; o < 8; o++) {
        float s = 0.0f;
        #pragma unroll
        for (int i = 0; i < 8; i++) s = fmaf(sw[o*8 + i], in[i], s);
        obase[(long)o * 65536] = s * sscale[o] + sshift[o];
    }
}

// ---------------- LayerNorm over (N,C) per batch ----------------
__global__ void ln_stats(const float* __restrict__ y, float* __restrict__ stats)
{
    __shared__ double rs[32], rq[32];
    int b = blockIdx.x;
    const float* p = y + (long)b * NC_;
    double s = 0.0, q = 0.0;
    for (int i = threadIdx.x; i < NC_; i += blockDim.x) {
        double v = (double)p[i];
        s += v; q += v * v;
    }
    #pragma unroll
    for (int o = 16; o > 0; o >>= 1) {
        s += __shfl_xor_sync(0xffffffffu, s, o);
        q += __shfl_xor_sync(0xffffffffu, q, o);
    }
    int lane = threadIdx.x & 31, wid = threadIdx.x >> 5;
    if (lane == 0) { rs[wid] = s; rq[wid] = q; }
    __syncthreads();
    if (threadIdx.x == 0) {
        double S = 0.0, Q = 0.0;
        for (int i = 0; i < (int)(blockDim.x >> 5); i++) { S += rs[i]; Q += rq[i]; }
        double mu  = S / (double)NC_;
        double var = Q / (double)NC_ - mu * mu;
        stats[b*2]   = (float)mu;
        stats[b*2+1] = (float)rsqrt(var + 1e-5);
    }
}

__global__ void ln_apply(const float* __restrict__ y, const float* __restrict__ stats,
                         const float* __restrict__ g, const float* __restrict__ beta,
                         float* __restrict__ out)
{
    long i = (long)blockIdx.x * blockDim.x + threadIdx.x;
    int b = (int)(i / NC_);
    int r = (int)(i % NC_);
    out[i] = (y[i] - stats[b*2]) * stats[b*2+1] * g[r] + beta[r];
}

// ---------------- launch ----------------
extern "C" void kernel_launch(void* const* d_in, const int* in_sizes, int n_in,
                              void* d_out, int out_size)
{
    const float* x        = (const float*)d_in[0];
    const float* qconv_w  = (const float*)d_in[1];
    const float* kconv_w  = (const float*)d_in[2];
    const float* vconv_w  = (const float*)d_in[3];
    const float* reat_w   = (const float*)d_in[4];
    const float* reat_b   = (const float*)d_in[5];
    const float* bn_gamma = (const float*)d_in[6];
    const float* bn_beta  = (const float*)d_in[7];
    const float* bn_mean  = (const float*)d_in[8];
    const float* bn_var   = (const float*)d_in[9];
    const float* proj_w   = (const float*)d_in[10];
    const float* proj_b   = (const float*)d_in[11];
    const float* ln_g     = (const float*)d_in[12];
    const float* ln_b     = (const float*)d_in[13];
    const float* ff_w1    = (const float*)d_in[14];
    const float* ff_b1    = (const float*)d_in[15];
    const float* ff_w2    = (const float*)d_in[16];
    const float* ff_b2    = (const float*)d_in[17];
    float* out = (float*)d_out;

    float *pq, *pk, *pv, *pattn, *pattn2, *pctx, *py1, *pyn, *py2, *ph, *pstats;
    cudaGetSymbolAddress((void**)&pq,     g_q);
    cudaGetSymbolAddress((void**)&pk,     g_k);
    cudaGetSymbolAddress((void**)&pv,     g_v);
    cudaGetSymbolAddress((void**)&pattn,  g_attn);
    cudaGetSymbolAddress((void**)&pattn2, g_attn2);
    cudaGetSymbolAddress((void**)&pctx,   g_ctx);
    cudaGetSymbolAddress((void**)&py1,    g_y1);
    cudaGetSymbolAddress((void**)&pyn,    g_yn);
    cudaGetSymbolAddress((void**)&py2,    g_y2);
    cudaGetSymbolAddress((void**)&ph,     g_h);
    cudaGetSymbolAddress((void**)&pstats, g_stats);

    // 1. conv QKV -> g_q/g_k/g_v in (B,H,N,hd)
    conv_qkv_kernel<<<B_*N_, 256>>>(x, qconv_w, kconv_w, vconv_w);

    // 2. S = Q K^T   (per (b,h): 256x256x384, NT)
    {
        dim3 grid(2, 2, BH_);
        sgemm128<true, 0><<<grid, 256>>>(pq, pk, pattn,
            N_, N_, HD_, HD_, HD_, N_,
            (long)N_*HD_, (long)N_*HD_, 1, 65536L, 0L, nullptr, nullptr);
    }

    // 3. softmax (with 1/sqrt(hd) scale)
    softmax256<<<BH_*N_, 256>>>(pattn, 0.051031036307982884f /* 384^-0.5 */);

    // 4. re-attention head mix + BN
    reatten_kernel<<<(B_*65536)/256, 256>>>(reat_w, reat_b, bn_gamma, bn_beta, bn_mean, bn_var);

    // 5. ctx = attn2 @ V, written directly into (B,N,C) layout
    {
        dim3 grid(3, 2, BH_);
        sgemm128<false, 0><<<grid, 256>>>(pattn2, pv, pctx,
            N_, HD_, N_, N_, HD_, C_,
            65536L, (long)N_*HD_, H_, (long)N_*C_, (long)HD_, nullptr, nullptr);
    }

    // 6. y1 = x + ctx @ proj_w + proj_b
    {
        dim3 grid(C_/128, (B_*N_)/128, 1);
        sgemm128<false, 3><<<grid, 256>>>(pctx, proj_w, py1,
            B_*N_, C_, C_, C_, C_, C_,
            0L, 0L, 1, 0L, 0L, proj_b, x);
    }

    // 7. LN1
    ln_stats<<<B_, 1024>>>(py1, pstats);
    ln_apply<<<QKV_SZ/256, 256>>>(py1, pstats, ln_g, ln_b, pyn);

    // 8. h = gelu(yn @ ff_w1 + b1)
    {
        dim3 grid(FF_/128, (B_*N_)/128, 1);
        sgemm128<false, 2><<<grid, 256>>>(pyn, ff_w1, ph,
            B_*N_, FF_, C_, C_, FF_, FF_,
            0L, 0L, 1, 0L, 0L, ff_b1, nullptr);
    }

    // 9. y2 = yn + h @ ff_w2 + b2
    {
        dim3 grid(C_/128, (B_*N_)/128, 1);
        sgemm128<false, 3><<<grid, 256>>>(ph, ff_w2, py2,
            B_*N_, C_, FF_, FF_, C_, C_,
            0L, 0L, 1, 0L, 0L, ff_b2, pyn);
    }

    // 10. LN2 -> out
    ln_stats<<<B_, 1024>>>(py2, pstats);
    ln_apply<<<QKV_SZ/256, 256>>>(py2, pstats, ln_g, ln_b, out);
}

// round 2
// speedup vs baseline: 3.1246x; 3.1246x over previous
#include <cuda_runtime.h>
#include <math.h>
#include <stdint.h>

// ---------------- problem constants ----------------
#define B_   8
#define N_   256
#define C_   3072
#define H_   8
#define HD_  384          // head dim
#define FF_  12288
#define P_   32           // patch spatial
#define NC_  (N_*C_)
#define BH_  (B_*H_)      // 64
#define QKV_SZ   (B_*N_*C_)          // 6291456
#define ATT_SZ   (B_*H_*N_*N_)       // 4194304
#define HBUF_SZ  (B_*N_*FF_)         // 25165824

// ---------------- device scratch ----------------
__device__ float g_q[QKV_SZ];
__device__ float g_kt[QKV_SZ];      // K stored transposed: (BH, hd, N)
__device__ float g_v[QKV_SZ];
__device__ float g_attn[ATT_SZ];
__device__ float g_attn2[ATT_SZ];
__device__ float g_ctx[QKV_SZ];
__device__ float g_y1[QKV_SZ];
__device__ float g_yn[QKV_SZ];
__device__ float g_y2[QKV_SZ];
__device__ float g_h[HBUF_SZ];
__device__ float g_stats[B_*2];

// ---------------- helpers ----------------
__device__ __forceinline__ float gelu_exact(float x) {
    return 0.5f * x * (1.0f + erff(x * 0.70710678118654752f));
}
__device__ __forceinline__ uint32_t f2tf32(float f) {
    uint32_t r;
    asm("cvt.rna.tf32.f32 %0, %1;" : "=r"(r) : "f"(f));
    return r;
}
__device__ __forceinline__ void cpa16(void* dst, const void* src) {
    uint32_t d = (uint32_t)__cvta_generic_to_shared(dst);
    asm volatile("cp.async.cg.shared.global [%0], [%1], 16;\n" :: "r"(d), "l"(src));
}
__device__ __forceinline__ void cp_commit() { asm volatile("cp.async.commit_group;\n"); }
template<int NN> __device__ __forceinline__ void cp_wait() {
    asm volatile("cp.async.wait_group %0;\n" :: "n"(NN));
}
__device__ __forceinline__ void mma_tf32(float c[4], uint32_t a0, uint32_t a1, uint32_t a2, uint32_t a3,
                                         uint32_t b0, uint32_t b1) {
    asm volatile(
        "mma.sync.aligned.m16n8k8.row.col.f32.tf32.tf32.f32 "
        "{%0,%1,%2,%3}, {%4,%5,%6,%7}, {%8,%9}, {%0,%1,%2,%3};\n"
        : "+f"(c[0]), "+f"(c[1]), "+f"(c[2]), "+f"(c[3])
        : "r"(a0), "r"(a1), "r"(a2), "r"(a3), "r"(b0), "r"(b1));
}

// ---------------- conv QKV ----------------
// one block per patch (B*N = 2048), 256 threads. K is written transposed.
__global__ void conv_qkv_kernel(const float* __restrict__ x,
                                const float* __restrict__ qw,
                                const float* __restrict__ kw,
                                const float* __restrict__ vw)
{
    __shared__ float sp[3][P_+2][P_+2];
    __shared__ float swq[81], swk[81], swv[81];
    int tid = threadIdx.x;
    int patch = blockIdx.x;
    int b = patch >> 8;
    int n = patch & 255;
    const float* xp = x + (long)patch * C_;

    if (tid < 81) { swq[tid] = qw[tid]; swk[tid] = kw[tid]; swv[tid] = vw[tid]; }
    for (int i = tid; i < 3*(P_+2)*(P_+2); i += 256)
        ((float*)sp)[i] = 0.0f;
    __syncthreads();
    for (int i = tid; i < C_; i += 256) {
        int ch = i >> 10;
        int s  = i & 1023;
        int yy = s >> 5, xx = s & 31;
        sp[ch][yy+1][xx+1] = xp[i];
    }
    __syncthreads();

    for (int pos = tid; pos < 1024; pos += 256) {
        int yy = pos >> 5, xx = pos & 31;
        float aq[3] = {0,0,0}, ak[3] = {0,0,0}, av[3] = {0,0,0};
        #pragma unroll
        for (int i = 0; i < 3; i++)
            #pragma unroll
            for (int dy = 0; dy < 3; dy++)
                #pragma unroll
                for (int dx = 0; dx < 3; dx++) {
                    float val = sp[i][yy+dy][xx+dx];
                    int wi = i*9 + dy*3 + dx;
                    #pragma unroll
                    for (int o = 0; o < 3; o++) {
                        aq[o] = fmaf(val, swq[o*27 + wi], aq[o]);
                        ak[o] = fmaf(val, swk[o*27 + wi], ak[o]);
                        av[o] = fmaf(val, swv[o*27 + wi], av[o]);
                    }
                }
        #pragma unroll
        for (int o = 0; o < 3; o++) {
            int c = o*1024 + pos;
            int h = c / HD_;
            int d = c - h*HD_;
            long bh = (long)(b*H_ + h);
            long dstqv = (bh*N_ + n)*HD_ + d;
            g_q[dstqv] = aq[o];
            g_v[dstqv] = av[o];
            g_kt[(bh*HD_ + d)*N_ + n] = ak[o];   // transposed for NN gemm
        }
    }
}

// ---------------- tf32 tensor-core GEMM (NN), 128x128x32 tiles ----------------
// EPI: 0 plain, 1 +bias, 2 +bias+gelu, 3 +bias+residual
#define AS_STRIDE 36
#define BS_STRIDE 136
#define AS_FLOATS (128*AS_STRIDE)     // per buffer
#define BS_FLOATS (32*BS_STRIDE)
#define SMEM_BYTES ((2*AS_FLOATS + 2*BS_FLOATS)*4)   // 71680

template<int EPI>
__global__ void __launch_bounds__(256, 2)
tgemm(const float* __restrict__ A, const float* __restrict__ Bm, float* __restrict__ C,
      int M, int N, int K, int lda, int ldb, int ldc,
      long sA, long sB, int zdiv, long sC1, long sC2,
      const float* __restrict__ bias, const float* __restrict__ resid)
{
    extern __shared__ float smem[];
    float* As = smem;                    // [2][128][AS_STRIDE]
    float* Bs = smem + 2*AS_FLOATS;      // [2][32][BS_STRIDE]

    int z = blockIdx.z;
    const float* Ab = A + (long)z * sA;
    const float* Bb = Bm + (long)z * sB;
    long coff = (long)(z / zdiv) * sC1 + (long)(z % zdiv) * sC2;
    float* Cb = C + coff;

    int tid = threadIdx.x;
    int lane = tid & 31, warp = tid >> 5;
    int wm = warp >> 2;     // 0..1 -> 64-row slab
    int wn = warp & 3;      // 0..3 -> 32-col slab
    int rowBlk = blockIdx.y * 128;
    int colBlk = blockIdx.x * 128;

    float acc[4][4][4];
    #pragma unroll
    for (int mi = 0; mi < 4; mi++)
        #pragma unroll
        for (int ni = 0; ni < 4; ni++)
            #pragma unroll
            for (int r = 0; r < 4; r++) acc[mi][ni][r] = 0.0f;

    int nt = K >> 5;   // K/32

    // copy indices
    int a_row = tid >> 1;             // not used directly; loop form below
    (void)a_row;

    auto load_tile = [&](int kt, int buf) {
        const float* Ag = Ab + (long)rowBlk * lda + kt*32;
        const float* Bg = Bb + (long)(kt*32) * ldb + colBlk;
        float* Asb = As + buf*AS_FLOATS;
        float* Bsb = Bs + buf*BS_FLOATS;
        #pragma unroll
        for (int it = 0; it < 4; it++) {
            int idx = tid + it*256;          // 0..1023
            int r = idx >> 3, k4 = (idx & 7) << 2;
            cpa16(Asb + r*AS_STRIDE + k4, Ag + (long)r*lda + k4);
        }
        #pragma unroll
        for (int it = 0; it < 4; it++) {
            int idx = tid + it*256;          // 0..1023
            int r = idx >> 5, n4 = (idx & 31) << 2;
            cpa16(Bsb + r*BS_STRIDE + n4, Bg + (long)r*ldb + n4);
        }
    };

    load_tile(0, 0);
    cp_commit();

    for (int kt = 0; kt < nt; kt++) {
        int cur = kt & 1;
        if (kt + 1 < nt) {
            load_tile(kt + 1, cur ^ 1);
            cp_commit();
            cp_wait<1>();
        } else {
            cp_wait<0>();
        }
        __syncthreads();

        const float* Asb = As + cur*AS_FLOATS;
        const float* Bsb = Bs + cur*BS_FLOATS;
        int g = lane >> 2, t4 = lane & 3;

        #pragma unroll
        for (int kk = 0; kk < 32; kk += 8) {
            uint32_t afr[4][4];
            #pragma unroll
            for (int mi = 0; mi < 4; mi++) {
                int row = wm*64 + mi*16 + g;
                const float* p = Asb + row*AS_STRIDE + kk + t4;
                afr[mi][0] = f2tf32(p[0]);
                afr[mi][1] = f2tf32(p[8*AS_STRIDE]);
                afr[mi][2] = f2tf32(p[4]);
                afr[mi][3] = f2tf32(p[8*AS_STRIDE + 4]);
            }
            uint32_t bfr[4][2];
            #pragma unroll
            for (int ni = 0; ni < 4; ni++) {
                int bcol = wn*32 + ni*8 + g;
                const float* p = Bsb + (kk + t4)*BS_STRIDE + bcol;
                bfr[ni][0] = f2tf32(p[0]);
                bfr[ni][1] = f2tf32(p[4*BS_STRIDE]);
            }
            #pragma unroll
            for (int mi = 0; mi < 4; mi++)
                #pragma unroll
                for (int ni = 0; ni < 4; ni++)
                    mma_tf32(acc[mi][ni], afr[mi][0], afr[mi][1], afr[mi][2], afr[mi][3],
                             bfr[ni][0], bfr[ni][1]);
        }
        __syncthreads();
    }

    // epilogue
    int g = lane >> 2, t4 = lane & 3;
    #pragma unroll
    for (int mi = 0; mi < 4; mi++) {
        #pragma unroll
        for (int ni = 0; ni < 4; ni++) {
            int r0 = rowBlk + wm*64 + mi*16 + g;
            int c0 = colBlk + wn*32 + ni*8 + 2*t4;
            float v0 = acc[mi][ni][0], v1 = acc[mi][ni][1];
            float v2 = acc[mi][ni][2], v3 = acc[mi][ni][3];
            if (EPI >= 1) {
                float b0 = bias[c0], b1 = bias[c0+1];
                v0 += b0; v1 += b1; v2 += b0; v3 += b1;
            }
            if (EPI == 2) {
                v0 = gelu_exact(v0); v1 = gelu_exact(v1);
                v2 = gelu_exact(v2); v3 = gelu_exact(v3);
            }
            if (EPI == 3) {
                const float* rp0 = resid + coff + (long)r0*ldc + c0;
                const float* rp1 = resid + coff + (long)(r0+8)*ldc + c0;
                v0 += rp0[0]; v1 += rp0[1];
                v2 += rp1[0]; v3 += rp1[1];
            }
            float2 w0 = make_float2(v0, v1);
            float2 w1 = make_float2(v2, v3);
            *(float2*)&Cb[(long)r0*ldc + c0]     = w0;
            *(float2*)&Cb[(long)(r0+8)*ldc + c0] = w1;
        }
    }
}

// ---------------- softmax over rows of length 256 ----------------
__global__ void softmax256(float* __restrict__ attn, float scale)
{
    __shared__ float red[8];
    long row = blockIdx.x;
    float* p = attn + row * 256;
    int tid = threadIdx.x;
    float v = p[tid] * scale;
    float m = v;
    #pragma unroll
    for (int o = 16; o > 0; o >>= 1) m = fmaxf(m, __shfl_xor_sync(0xffffffffu, m, o));
    if ((tid & 31) == 0) red[tid >> 5] = m;
    __syncthreads();
    float bm = red[0];
    #pragma unroll
    for (int i = 1; i < 8; i++) bm = fmaxf(bm, red[i]);
    float e = __expf(v - bm);
    float s = e;
    #pragma unroll
    for (int o = 16; o > 0; o >>= 1) s += __shfl_xor_sync(0xffffffffu, s, o);
    __syncthreads();
    if ((tid & 31) == 0) red[tid >> 5] = s;
    __syncthreads();
    float bs = 0.0f;
    #pragma unroll
    for (int i = 0; i < 8; i++) bs += red[i];
    p[tid] = e / bs;
}

// ---------------- re-attention (head mix + BN) ----------------
__global__ void reatten_kernel(const float* __restrict__ w,  const float* __restrict__ rb,
                               const float* __restrict__ g,  const float* __restrict__ bta,
                               const float* __restrict__ mean, const float* __restrict__ var)
{
    __shared__ float sw[64], sscale[8], sshift[8];
    int tid = threadIdx.x;
    if (tid < 64) sw[tid] = w[tid];
    if (tid < 8) {
        float inv = rsqrtf(var[tid] + 1e-5f);
        float gi = g[tid] * inv;
        sscale[tid] = gi;
        sshift[tid] = bta[tid] + (rb[tid] - mean[tid]) * gi;
    }
    __syncthreads();
    long idx = (long)blockIdx.x * blockDim.x + tid;
    int b  = (int)(idx >> 16);
    int nm = (int)(idx & 65535);
    const float* base = g_attn + ((long)b * H_) * 65536 + nm;
    float in[8];
    #pragma unroll
    for (int i = 0; i < 8; i++) in[i] = base[(long)i * 65536];
    float* obase = g_attn2 + ((long)b * H_) * 65536 + nm;
    #pragma unroll
    for (int o = 0; o < 8; o++) {
        float s = 0.0f;
        #pragma unroll
        for (int i = 0; i < 8; i++) s = fmaf(sw[o*8 + i], in[i], s);
        obase[(long)o * 65536] = s * sscale[o] + sshift[o];
    }
}

// ---------------- LayerNorm over (N,C) per batch ----------------
__global__ void ln_stats(const float* __restrict__ y, float* __restrict__ stats)
{
    __shared__ double rs[32], rq[32];
    int b = blockIdx.x;
    const float* p = y + (long)b * NC_;
    double s = 0.0, q = 0.0;
    for (int i = threadIdx.x; i < NC_; i += blockDim.x) {
        double v = (double)p[i];
        s += v; q += v * v;
    }
    #pragma unroll
    for (int o = 16; o > 0; o >>= 1) {
        s += __shfl_xor_sync(0xffffffffu, s, o);
        q += __shfl_xor_sync(0xffffffffu, q, o);
    }
    int lane = threadIdx.x & 31, wid = threadIdx.x >> 5;
    if (lane == 0) { rs[wid] = s; rq[wid] = q; }
    __syncthreads();
    if (threadIdx.x == 0) {
        double S = 0.0, Q = 0.0;
        for (int i = 0; i < (int)(blockDim.x >> 5); i++) { S += rs[i]; Q += rq[i]; }
        double mu  = S / (double)NC_;
        double var = Q / (double)NC_ - mu * mu;
        stats[b*2]   = (float)mu;
        stats[b*2+1] = (float)rsqrt(var + 1e-5);
    }
}

__global__ void ln_apply(const float* __restrict__ y, const float* __restrict__ stats,
                         const float* __restrict__ g, const float* __restrict__ beta,
                         float* __restrict__ out)
{
    long i = (long)blockIdx.x * blockDim.x + threadIdx.x;
    int b = (int)(i / NC_);
    int r = (int)(i % NC_);
    out[i] = (y[i] - stats[b*2]) * stats[b*2+1] * g[r] + beta[r];
}

// ---------------- launch ----------------
extern "C" void kernel_launch(void* const* d_in, const int* in_sizes, int n_in,
                              void* d_out, int out_size)
{
    const float* x        = (const float*)d_in[0];
    const float* qconv_w  = (const float*)d_in[1];
    const float* kconv_w  = (const float*)d_in[2];
    const float* vconv_w  = (const float*)d_in[3];
    const float* reat_w   = (const float*)d_in[4];
    const float* reat_b   = (const float*)d_in[5];
    const float* bn_gamma = (const float*)d_in[6];
    const float* bn_beta  = (const float*)d_in[7];
    const float* bn_mean  = (const float*)d_in[8];
    const float* bn_var   = (const float*)d_in[9];
    const float* proj_w   = (const float*)d_in[10];
    const float* proj_b   = (const float*)d_in[11];
    const float* ln_g     = (const float*)d_in[12];
    const float* ln_b     = (const float*)d_in[13];
    const float* ff_w1    = (const float*)d_in[14];
    const float* ff_b1    = (const float*)d_in[15];
    const float* ff_w2    = (const float*)d_in[16];
    const float* ff_b2    = (const float*)d_in[17];
    float* out = (float*)d_out;

    float *pq, *pkt, *pv, *pattn, *pattn2, *pctx, *py1, *pyn, *py2, *ph, *pstats;
    cudaGetSymbolAddress((void**)&pq,     g_q);
    cudaGetSymbolAddress((void**)&pkt,    g_kt);
    cudaGetSymbolAddress((void**)&pv,     g_v);
    cudaGetSymbolAddress((void**)&pattn,  g_attn);
    cudaGetSymbolAddress((void**)&pattn2, g_attn2);
    cudaGetSymbolAddress((void**)&pctx,   g_ctx);
    cudaGetSymbolAddress((void**)&py1,    g_y1);
    cudaGetSymbolAddress((void**)&pyn,    g_yn);
    cudaGetSymbolAddress((void**)&py2,    g_y2);
    cudaGetSymbolAddress((void**)&ph,     g_h);
    cudaGetSymbolAddress((void**)&pstats, g_stats);

    cudaFuncSetAttribute(tgemm<0>, cudaFuncAttributeMaxDynamicSharedMemorySize, SMEM_BYTES);
    cudaFuncSetAttribute(tgemm<2>, cudaFuncAttributeMaxDynamicSharedMemorySize, SMEM_BYTES);
    cudaFuncSetAttribute(tgemm<3>, cudaFuncAttributeMaxDynamicSharedMemorySize, SMEM_BYTES);

    // 1. conv QKV -> g_q/g_v (BH,N,hd), g_kt (BH,hd,N)
    conv_qkv_kernel<<<B_*N_, 256>>>(x, qconv_w, kconv_w, vconv_w);

    // 2. S = Q @ Kt  (per bh: 256x256x384, NN)
    {
        dim3 grid(2, 2, BH_);
        tgemm<0><<<grid, 256, SMEM_BYTES>>>(pq, pkt, pattn,
            N_, N_, HD_, HD_, N_, N_,
            (long)N_*HD_, (long)N_*HD_, 1, 65536L, 0L, nullptr, nullptr);
    }

    // 3. softmax (with 1/sqrt(hd) scale)
    softmax256<<<BH_*N_, 256>>>(pattn, 0.051031036307982884f);

    // 4. re-attention head mix + BN
    reatten_kernel<<<(B_*65536)/256, 256>>>(reat_w, reat_b, bn_gamma, bn_beta, bn_mean, bn_var);

    // 5. ctx = attn2 @ V, written into (B,N,C) layout
    {
        dim3 grid(3, 2, BH_);
        tgemm<0><<<grid, 256, SMEM_BYTES>>>(pattn2, pv, pctx,
            N_, HD_, N_, N_, HD_, C_,
            65536L, (long)N_*HD_, H_, (long)N_*C_, (long)HD_, nullptr, nullptr);
    }

    // 6. y1 = x + ctx @ proj_w + proj_b
    {
        dim3 grid(C_/128, (B_*N_)/128, 1);
        tgemm<3><<<grid, 256, SMEM_BYTES>>>(pctx, proj_w, py1,
            B_*N_, C_, C_, C_, C_, C_,
            0L, 0L, 1, 0L, 0L, proj_b, x);
    }

    // 7. LN1
    ln_stats<<<B_, 1024>>>(py1, pstats);
    ln_apply<<<QKV_SZ/256, 256>>>(py1, pstats, ln_g, ln_b, pyn);

    // 8. h = gelu(yn @ ff_w1 + b1)
    {
        dim3 grid(FF_/128, (B_*N_)/128, 1);
        tgemm<2><<<grid, 256, SMEM_BYTES>>>(pyn, ff_w1, ph,
            B_*N_, FF_, C_, C_, FF_, FF_,
            0L, 0L, 1, 0L, 0L, ff_b1, nullptr);
    }

    // 9. y2 = yn + h @ ff_w2 + b2
    {
        dim3 grid(C_/128, (B_*N_)/128, 1);
        tgemm<3><<<grid, 256, SMEM_BYTES>>>(ph, ff_w2, py2,
            B_*N_, C_, FF_, FF_, C_, C_,
            0L, 0L, 1, 0L, 0L, ff_b2, pyn);
    }

    // 10. LN2 -> out
    ln_stats<<<B_, 1024>>>(py2, pstats);
    ln_apply<<<QKV_SZ/256, 256>>>(py2, pstats, ln_g, ln_b, out);
}

// round 4
// speedup vs baseline: 4.4086x; 1.4109x over previous
#include <cuda_runtime.h>
#include <cuda_fp16.h>
#include <math.h>
#include <stdint.h>

// ---------------- problem constants ----------------
#define B_   8
#define N_   256
#define C_   3072
#define H_   8
#define HD_  384
#define FF_  12288
#define P_   32
#define NC_  (N_*C_)
#define BH_  (B_*H_)
#define QKV_SZ   (B_*N_*C_)
#define ATT_SZ   (B_*H_*N_*N_)
#define HBUF_SZ  (B_*N_*FF_)

// ---------------- device scratch ----------------
__device__ __align__(256) __half g_hq[QKV_SZ];
__device__ __align__(256) __half g_hk[QKV_SZ];
__device__ __align__(256) __half g_hvt[QKV_SZ];     // V^T: (BH, hd, N)
__device__ __align__(256) __half g_hattn2[ATT_SZ];
__device__ __align__(256) __half g_hctx[QKV_SZ];
__device__ __align__(256) __half g_hynh[QKV_SZ];
__device__ __align__(256) __half g_hh[HBUF_SZ];
__device__ __align__(256) __half g_hprojT[C_*C_];
__device__ __align__(256) __half g_hw1T[(long)C_*FF_];
__device__ __align__(256) __half g_hw2T[(long)C_*FF_];
__device__ float g_attn[ATT_SZ];
__device__ float g_y1[QKV_SZ];
__device__ float g_yn[QKV_SZ];
__device__ float g_y2[QKV_SZ];
__device__ float g_stats[B_*2];

// ---------------- helpers ----------------
__device__ __forceinline__ float gelu_exact(float x) {
    return 0.5f * x * (1.0f + erff(x * 0.70710678118654752f));
}
__device__ __forceinline__ uint32_t smem_u32(const void* p) {
    return (uint32_t)__cvta_generic_to_shared(p);
}
__device__ __forceinline__ void cpa16(uint32_t dst, const void* src) {
    asm volatile("cp.async.cg.shared.global [%0], [%1], 16;\n" :: "r"(dst), "l"(src));
}
__device__ __forceinline__ void cp_commit() { asm volatile("cp.async.commit_group;\n"); }
template<int NN> __device__ __forceinline__ void cp_wait() {
    asm volatile("cp.async.wait_group %0;\n" :: "n"(NN));
}
__device__ __forceinline__ void ldsm_x4(uint32_t* r, uint32_t addr) {
    asm volatile("ldmatrix.sync.aligned.m8n8.x4.shared.b16 {%0,%1,%2,%3}, [%4];"
                 : "=r"(r[0]), "=r"(r[1]), "=r"(r[2]), "=r"(r[3]) : "r"(addr));
}
__device__ __forceinline__ void mma_f16(float c[4], uint32_t a0, uint32_t a1, uint32_t a2,
                                        uint32_t a3, uint32_t b0, uint32_t b1) {
    asm volatile(
        "mma.sync.aligned.m16n8k16.row.col.f32.f16.f16.f32 "
        "{%0,%1,%2,%3},{%4,%5,%6,%7},{%8,%9},{%0,%1,%2,%3};\n"
        : "+f"(c[0]), "+f"(c[1]), "+f"(c[2]), "+f"(c[3])
        : "r"(a0), "r"(a1), "r"(a2), "r"(a3), "r"(b0), "r"(b1));
}

// ================= fp16 tensor-core GEMM =================
// C[m][n] = sum_k A[m][k] * B[n][k]; A,B fp16 (M/N-major, K contiguous), acc fp32.
// 128x128 CTA tile, BK=64, 2-stage cp.async pipeline, ldmatrix fragments.
// EPI: 0 plain->half, 1 plain->float, 2 bias+gelu->half, 3 bias+resid->float
#define ASZ  (128*72*2)       // 18432 B per A tile
#define STG  (2*ASZ)          // 36864 B per stage (A+B)
#define HSMEM (2*STG)         // 73728 B

template<int EPI, typename OutT>
__global__ void __launch_bounds__(256, 2)
hgemm(const __half* __restrict__ A, const __half* __restrict__ Bm, OutT* __restrict__ C,
      int K, int lda, int ldb, int ldc,
      long sA, long sB, int zdiv, long sC1, long sC2,
      const float* __restrict__ bias, const float* __restrict__ resid)
{
    extern __shared__ char smem[];
    const uint32_t sbase = smem_u32(smem);

    int tid = threadIdx.x;
    int warp = tid >> 5, lane = tid & 31;
    int wm = warp >> 2, wn = warp & 3;      // 2 x 4 warp grid, 64x32 warp tile
    int z = blockIdx.z;
    const __half* Ab = A + (long)z * sA;
    const __half* Bb = Bm + (long)z * sB;
    long coff = (long)(z / zdiv) * sC1 + (long)(z % zdiv) * sC2;
    OutT* Cb = C + coff;
    int rowBlk = blockIdx.y * 128;
    int colBlk = blockIdx.x * 128;

    float acc[4][4][4];
    #pragma unroll
    for (int mi = 0; mi < 4; mi++)
        #pragma unroll
        for (int ni = 0; ni < 4; ni++)
            #pragma unroll
            for (int r = 0; r < 4; r++) acc[mi][ni][r] = 0.0f;

    // per-thread ldmatrix base offsets (bytes), row stride = 72 halfs = 144 B
    uint32_t aoff = (uint32_t)(((wm*64 + (lane & 15)) * 72 + ((lane >> 4) << 3)) * 2);
    uint32_t boff0 = (uint32_t)(((wn*32 + (lane & 7) + ((lane >> 4) << 3)) * 72 + (lane & 8)) * 2);
    uint32_t boff1 = boff0 + 16u*144u;

    auto load_chunk = [&](int ck, int s) {
        uint32_t ab = sbase + s*STG;
        uint32_t bb = ab + ASZ;
        const __half* Ag = Ab + (long)rowBlk * lda + ck*64;
        const __half* Bg = Bb + (long)colBlk * ldb + ck*64;
        #pragma unroll
        for (int it = 0; it < 4; it++) {
            int idx = tid + it*256;             // 0..1023
            int row = idx >> 3, gq = idx & 7;
            cpa16(ab + row*144 + gq*16, Ag + (long)row*lda + gq*8);
        }
        #pragma unroll
        for (int it = 0; it < 4; it++) {
            int idx = tid + it*256;
            int row = idx >> 3, gq = idx & 7;
            cpa16(bb + row*144 + gq*16, Bg + (long)row*ldb + gq*8);
        }
        cp_commit();
    };

    int nc = K >> 6;
    load_chunk(0, 0);

    for (int c = 0; c < nc; c++) {
        int s = c & 1;
        if (c + 1 < nc) { load_chunk(c + 1, s ^ 1); cp_wait<1>(); }
        else            { cp_wait<0>(); }
        __syncthreads();

        uint32_t As = sbase + s*STG;
        uint32_t Bs = As + ASZ;
        #pragma unroll
        for (int kk = 0; kk < 64; kk += 16) {
            uint32_t a[4][4], b[2][4];
            #pragma unroll
            for (int mi = 0; mi < 4; mi++)
                ldsm_x4(a[mi], As + aoff + mi*2304u + kk*2);
            ldsm_x4(b[0], Bs + boff0 + kk*2);
            ldsm_x4(b[1], Bs + boff1 + kk*2);
            #pragma unroll
            for (int mi = 0; mi < 4; mi++)
                #pragma unroll
                for (int ni = 0; ni < 4; ni++)
                    mma_f16(acc[mi][ni], a[mi][0], a[mi][1], a[mi][2], a[mi][3],
                            b[ni >> 1][(ni & 1)*2], b[ni >> 1][(ni & 1)*2 + 1]);
        }
        __syncthreads();
    }

    // ---------------- epilogue ----------------
    int g = lane >> 2, t4 = lane & 3;
    #pragma unroll
    for (int mi = 0; mi < 4; mi++) {
        #pragma unroll
        for (int ni = 0; ni < 4; ni++) {
            int r0 = rowBlk + wm*64 + mi*16 + g;
            int c0 = colBlk + wn*32 + ni*8 + 2*t4;
            float v0 = acc[mi][ni][0], v1 = acc[mi][ni][1];
            float v2 = acc[mi][ni][2], v3 = acc[mi][ni][3];
            if (EPI >= 2) {
                float b0 = bias[c0], b1 = bias[c0+1];
                v0 += b0; v1 += b1; v2 += b0; v3 += b1;
            }
            if (EPI == 2) {
                v0 = gelu_exact(v0); v1 = gelu_exact(v1);
                v2 = gelu_exact(v2); v3 = gelu_exact(v3);
            }
            if (EPI == 3) {
                const float2 ra = *(const float2*)&resid[coff + (long)r0*ldc + c0];
                const float2 rb = *(const float2*)&resid[coff + (long)(r0+8)*ldc + c0];
                v0 += ra.x; v1 += ra.y; v2 += rb.x; v3 += rb.y;
            }
            if (EPI == 0 || EPI == 2) {
                *(__half2*)&((__half*)Cb)[(long)r0*ldc + c0]     = __floats2half2_rn(v0, v1);
                *(__half2*)&((__half*)Cb)[(long)(r0+8)*ldc + c0] = __floats2half2_rn(v2, v3);
            } else {
                *(float2*)&((float*)Cb)[(long)r0*ldc + c0]     = make_float2(v0, v1);
                *(float2*)&((float*)Cb)[(long)(r0+8)*ldc + c0] = make_float2(v2, v3);
            }
        }
    }
}

// ---------------- transpose fp32 -> fp16 ----------------
__global__ void transpose_h(const float* __restrict__ src, __half* __restrict__ dst,
                            int R, int Ccol)
{
    __shared__ float t[32][33];
    int c0 = blockIdx.x * 32, r0 = blockIdx.y * 32;
    int x = c0 + threadIdx.x;
    #pragma unroll
    for (int j = threadIdx.y; j < 32; j += 8)
        t[j][threadIdx.x] = src[(long)(r0 + j) * Ccol + x];
    __syncthreads();
    int x2 = r0 + threadIdx.x;
    #pragma unroll
    for (int j = threadIdx.y; j < 32; j += 8)
        dst[(long)(c0 + j) * R + x2] = __float2half_rn(t[threadIdx.x][j]);
}

// ---------------- conv QKV ----------------
__global__ void conv_qkv_kernel(const float* __restrict__ x,
                                const float* __restrict__ qw,
                                const float* __restrict__ kw,
                                const float* __restrict__ vw)
{
    __shared__ float sp[3][P_+2][P_+2];
    __shared__ float swq[81], swk[81], swv[81];
    int tid = threadIdx.x;
    int patch = blockIdx.x;
    int b = patch >> 8;
    int n = patch & 255;
    const float* xp = x + (long)patch * C_;

    if (tid < 81) { swq[tid] = qw[tid]; swk[tid] = kw[tid]; swv[tid] = vw[tid]; }
    for (int i = tid; i < 3*(P_+2)*(P_+2); i += 256)
        ((float*)sp)[i] = 0.0f;
    __syncthreads();
    for (int i = tid; i < C_; i += 256) {
        int ch = i >> 10;
        int s  = i & 1023;
        int yy = s >> 5, xx = s & 31;
        sp[ch][yy+1][xx+1] = xp[i];
    }
    __syncthreads();

    for (int pos = tid; pos < 1024; pos += 256) {
        int yy = pos >> 5, xx = pos & 31;
        float aq[3] = {0,0,0}, ak[3] = {0,0,0}, av[3] = {0,0,0};
        #pragma unroll
        for (int i = 0; i < 3; i++)
            #pragma unroll
            for (int dy = 0; dy < 3; dy++)
                #pragma unroll
                for (int dx = 0; dx < 3; dx++) {
                    float val = sp[i][yy+dy][xx+dx];
                    int wi = i*9 + dy*3 + dx;
                    #pragma unroll
                    for (int o = 0; o < 3; o++) {
                        aq[o] = fmaf(val, swq[o*27 + wi], aq[o]);
                        ak[o] = fmaf(val, swk[o*27 + wi], ak[o]);
                        av[o] = fmaf(val, swv[o*27 + wi], av[o]);
                    }
                }
        #pragma unroll
        for (int o = 0; o < 3; o++) {
            int c = o*1024 + pos;
            int h = c / HD_;
            int d = c - h*HD_;
            long bh = (long)(b*H_ + h);
            long dstq = (bh*N_ + n)*HD_ + d;
            g_hq[dstq] = __float2half_rn(aq[o]);
            g_hk[dstq] = __float2half_rn(ak[o]);
            g_hvt[(bh*HD_ + d)*N_ + n] = __float2half_rn(av[o]);
        }
    }
}

// ---------------- softmax over rows of length 256 ----------------
__global__ void softmax256(float* __restrict__ attn, float scale)
{
    __shared__ float red[8];
    long row = blockIdx.x;
    float* p = attn + row * 256;
    int tid = threadIdx.x;
    float v = p[tid] * scale;
    float m = v;
    #pragma unroll
    for (int o = 16; o > 0; o >>= 1) m = fmaxf(m, __shfl_xor_sync(0xffffffffu, m, o));
    if ((tid & 31) == 0) red[tid >> 5] = m;
    __syncthreads();
    float bm = red[0];
    #pragma unroll
    for (int i = 1; i < 8; i++) bm = fmaxf(bm, red[i]);
    float e = __expf(v - bm);
    float s = e;
    #pragma unroll
    for (int o = 16; o > 0; o >>= 1) s += __shfl_xor_sync(0xffffffffu, s, o);
    __syncthreads();
    if ((tid & 31) == 0) red[tid >> 5] = s;
    __syncthreads();
    float bs = 0.0f;
    #pragma unroll
    for (int i = 0; i < 8; i++) bs += red[i];
    p[tid] = e / bs;
}

// ---------------- re-attention (head mix + BN) -> fp16 ----------------
__global__ void reatten_kernel(const float* __restrict__ w,  const float* __restrict__ rb,
                               const float* __restrict__ g,  const float* __restrict__ bta,
                               const float* __restrict__ mean, const float* __restrict__ var)
{
    __shared__ float sw[64], sscale[8], sshift[8];
    int tid = threadIdx.x;
    if (tid < 64) sw[tid] = w[tid];
    if (tid < 8) {
        float inv = rsqrtf(var[tid] + 1e-5f);
        float gi = g[tid] * inv;
        sscale[tid] = gi;
        sshift[tid] = bta[tid] + (rb[tid] - mean[tid]) * gi;
    }
    __syncthreads();
    long idx = (long)blockIdx.x * blockDim.x + tid;
    int b  = (int)(idx >> 16);
    int nm = (int)(idx & 65535);
    const float* base = g_attn + ((long)b * H_) * 65536 + nm;
    float in[8];
    #pragma unroll
    for (int i = 0; i < 8; i++) in[i] = base[(long)i * 65536];
    __half* obase = g_hattn2 + ((long)b * H_) * 65536 + nm;
    #pragma unroll
    for (int o = 0; o < 8; o++) {
        float s = 0.0f;
        #pragma unroll
        for (int i = 0; i < 8; i++) s = fmaf(sw[o*8 + i], in[i], s);
        obase[(long)o * 65536] = __float2half_rn(s * sscale[o] + sshift[o]);
    }
}

// ---------------- LayerNorm over (N,C) per batch ----------------
__global__ void ln_stats(const float* __restrict__ y, float* __restrict__ stats)
{
    __shared__ double rs[32], rq[32];
    int b = blockIdx.x;
    const float* p = y + (long)b * NC_;
    double s = 0.0, q = 0.0;
    for (int i = threadIdx.x; i < NC_; i += blockDim.x) {
        double v = (double)p[i];
        s += v; q += v * v;
    }
    #pragma unroll
    for (int o = 16; o > 0; o >>= 1) {
        s += __shfl_xor_sync(0xffffffffu, s, o);
        q += __shfl_xor_sync(0xffffffffu, q, o);
    }
    int lane = threadIdx.x & 31, wid = threadIdx.x >> 5;
    if (lane == 0) { rs[wid] = s; rq[wid] = q; }
    __syncthreads();
    if (threadIdx.x == 0) {
        double S = 0.0, Q = 0.0;
        for (int i = 0; i < (int)(blockDim.x >> 5); i++) { S += rs[i]; Q += rq[i]; }
        double mu  = S / (double)NC_;
        double var = Q / (double)NC_ - mu * mu;
        stats[b*2]   = (float)mu;
        stats[b*2+1] = (float)rsqrt(var + 1e-5);
    }
}

// LN apply writing fp32 (residual path) + fp16 (GEMM operand)
__global__ void ln_apply_dual(const float* __restrict__ y, const float* __restrict__ stats,
                              const float* __restrict__ g, const float* __restrict__ beta,
                              float* __restrict__ outf, __half* __restrict__ outh)
{
    long i = (long)blockIdx.x * blockDim.x + threadIdx.x;
    int b = (int)(i / NC_);
    int r = (int)(i % NC_);
    float v = (y[i] - stats[b*2]) * stats[b*2+1] * g[r] + beta[r];
    outf[i] = v;
    outh[i] = __float2half_rn(v);
}

__global__ void ln_apply(const float* __restrict__ y, const float* __restrict__ stats,
                         const float* __restrict__ g, const float* __restrict__ beta,
                         float* __restrict__ out)
{
    long i = (long)blockIdx.x * blockDim.x + threadIdx.x;
    int b = (int)(i / NC_);
    int r = (int)(i % NC_);
    out[i] = (y[i] - stats[b*2]) * stats[b*2+1] * g[r] + beta[r];
}

// ---------------- launch ----------------
extern "C" void kernel_launch(void* const* d_in, const int* in_sizes, int n_in,
                              void* d_out, int out_size)
{
    const float* x        = (const float*)d_in[0];
    const float* qconv_w  = (const float*)d_in[1];
    const float* kconv_w  = (const float*)d_in[2];
    const float* vconv_w  = (const float*)d_in[3];
    const float* reat_w   = (const float*)d_in[4];
    const float* reat_b   = (const float*)d_in[5];
    const float* bn_gamma = (const float*)d_in[6];
    const float* bn_beta  = (const float*)d_in[7];
    const float* bn_mean  = (const float*)d_in[8];
    const float* bn_var   = (const float*)d_in[9];
    const float* proj_w   = (const float*)d_in[10];
    const float* proj_b   = (const float*)d_in[11];
    const float* ln_g     = (const float*)d_in[12];
    const float* ln_b     = (const float*)d_in[13];
    const float* ff_w1    = (const float*)d_in[14];
    const float* ff_b1    = (const float*)d_in[15];
    const float* ff_w2    = (const float*)d_in[16];
    const float* ff_b2    = (const float*)d_in[17];
    float* out = (float*)d_out;

    __half *pq, *pk, *pvt, *pattn2, *pctx, *pynh, *ph, *pprojT, *pw1T, *pw2T;
    float *pattn, *py1, *pyn, *py2, *pstats;
    cudaGetSymbolAddress((void**)&pq,     g_hq);
    cudaGetSymbolAddress((void**)&pk,     g_hk);
    cudaGetSymbolAddress((void**)&pvt,    g_hvt);
    cudaGetSymbolAddress((void**)&pattn2, g_hattn2);
    cudaGetSymbolAddress((void**)&pctx,   g_hctx);
    cudaGetSymbolAddress((void**)&pynh,   g_hynh);
    cudaGetSymbolAddress((void**)&ph,     g_hh);
    cudaGetSymbolAddress((void**)&pprojT, g_hprojT);
    cudaGetSymbolAddress((void**)&pw1T,   g_hw1T);
    cudaGetSymbolAddress((void**)&pw2T,   g_hw2T);
    cudaGetSymbolAddress((void**)&pattn,  g_attn);
    cudaGetSymbolAddress((void**)&py1,    g_y1);
    cudaGetSymbolAddress((void**)&pyn,    g_yn);
    cudaGetSymbolAddress((void**)&py2,    g_y2);
    cudaGetSymbolAddress((void**)&pstats, g_stats);

    cudaFuncSetAttribute(hgemm<0,__half>, cudaFuncAttributeMaxDynamicSharedMemorySize, HSMEM);
    cudaFuncSetAttribute(hgemm<1,float>,  cudaFuncAttributeMaxDynamicSharedMemorySize, HSMEM);
    cudaFuncSetAttribute(hgemm<2,__half>, cudaFuncAttributeMaxDynamicSharedMemorySize, HSMEM);
    cudaFuncSetAttribute(hgemm<3,float>,  cudaFuncAttributeMaxDynamicSharedMemorySize, HSMEM);

    // 0. weight transposes (fp32 -> fp16, B layout [n][k])
    {
        dim3 blk(32, 8);
        transpose_h<<<dim3(C_/32, C_/32), blk>>>(proj_w, pprojT, C_, C_);
        transpose_h<<<dim3(FF_/32, C_/32), blk>>>(ff_w1, pw1T, C_, FF_);
        transpose_h<<<dim3(C_/32, FF_/32), blk>>>(ff_w2, pw2T, FF_, C_);
    }

    // 1. conv QKV -> q,k (BH,N,hd) fp16, vt (BH,hd,N) fp16
    conv_qkv_kernel<<<B_*N_, 256>>>(x, qconv_w, kconv_w, vconv_w);

    // 2. S = Q K^T  (per bh: 256x256x384) -> fp32 attn
    hgemm<1,float><<<dim3(2,2,BH_), 256, HSMEM>>>(pq, pk, pattn,
        HD_, HD_, HD_, N_, (long)N_*HD_, (long)N_*HD_, 1, 65536L, 0L, nullptr, nullptr);

    // 3. softmax
    softmax256<<<BH_*N_, 256>>>(pattn, 0.051031036307982884f);

    // 4. re-attention head mix + BN -> fp16 attn2
    reatten_kernel<<<(B_*65536)/256, 256>>>(reat_w, reat_b, bn_gamma, bn_beta, bn_mean, bn_var);

    // 5. ctx = attn2 @ V  (per bh: 256x384x256) -> fp16 (B,N,C) layout
    hgemm<0,__half><<<dim3(3,2,BH_), 256, HSMEM>>>(pattn2, pvt, pctx,
        N_, N_, N_, C_, 65536L, (long)HD_*N_, H_, (long)N_*C_, (long)HD_, nullptr, nullptr);

    // 6. y1 = x + ctx @ proj_w + proj_b   (2048x3072x3072)
    hgemm<3,float><<<dim3(C_/128, (B_*N_)/128, 1), 256, HSMEM>>>(pctx, pprojT, py1,
        C_, C_, C_, C_, 0L, 0L, 1, 0L, 0L, proj_b, x);

    // 7. LN1 -> yn (fp32) + ynh (fp16)
    ln_stats<<<B_, 1024>>>(py1, pstats);
    ln_apply_dual<<<QKV_SZ/256, 256>>>(py1, pstats, ln_g, ln_b, pyn, pynh);

    // 8. h = gelu(yn @ ff_w1 + b1)   (2048x12288x3072) -> fp16
    hgemm<2,__half><<<dim3(FF_/128, (B_*N_)/128, 1), 256, HSMEM>>>(pynh, pw1T, ph,
        C_, C_, C_, FF_, 0L, 0L, 1, 0L, 0L, ff_b1, nullptr);

    // 9. y2 = yn + h @ ff_w2 + b2    (2048x3072x12288)
    hgemm<3,float><<<dim3(C_/128, (B_*N_)/128, 1), 256, HSMEM>>>(ph, pw2T, py2,
        FF_, FF_, FF_, C_, 0L, 0L, 1, 0L, 0L, ff_b2, pyn);

    // 10. LN2 -> out
    ln_stats<<<B_, 1024>>>(py2, pstats);
    ln_apply<<<QKV_SZ/256, 256>>>(py2, pstats, ln_g, ln_b, out);
}

// round 5
// speedup vs baseline: 6.5997x; 1.4970x over previous
#include <cuda_runtime.h>
#include <cuda_fp16.h>
#include <math.h>
#include <stdint.h>

// ---------------- problem constants ----------------
#define B_   8
#define N_   256
#define C_   3072
#define H_   8
#define HD_  384
#define FF_  12288
#define P_   32
#define NC_  (N_*C_)
#define BH_  (B_*H_)
#define QKV_SZ   (B_*N_*C_)
#define ATT_SZ   (B_*H_*N_*N_)
#define HBUF_SZ  (B_*N_*FF_)

// ---------------- device scratch ----------------
__device__ __align__(256) __half g_hq[QKV_SZ];
__device__ __align__(256) __half g_hk[QKV_SZ];
__device__ __align__(256) __half g_hvt[QKV_SZ];     // V^T: (BH, hd, N)
__device__ __align__(256) __half g_hattn2[ATT_SZ];
__device__ __align__(256) __half g_hctx[QKV_SZ];
__device__ __align__(256) __half g_hynh[QKV_SZ];
__device__ __align__(256) __half g_hh[HBUF_SZ];
__device__ __align__(256) __half g_hprojT[C_*C_];
__device__ __align__(256) __half g_hw1T[(long)C_*FF_];
__device__ __align__(256) __half g_hw2T[(long)C_*FF_];
__device__ float g_attn[ATT_SZ];
__device__ float g_y1[QKV_SZ];
__device__ float g_yn[QKV_SZ];
__device__ float g_y2[QKV_SZ];
__device__ float g_stats[B_*2];
__device__ double g_part[B_*32*2];

// ---------------- helpers ----------------
__device__ __forceinline__ float gelu_exact(float x) {
    return 0.5f * x * (1.0f + erff(x * 0.70710678118654752f));
}
__device__ __forceinline__ uint32_t smem_u32(const void* p) {
    return (uint32_t)__cvta_generic_to_shared(p);
}
__device__ __forceinline__ void cpa16(uint32_t dst, const void* src) {
    asm volatile("cp.async.cg.shared.global [%0], [%1], 16;\n" :: "r"(dst), "l"(src));
}
__device__ __forceinline__ void cp_commit() { asm volatile("cp.async.commit_group;\n"); }
template<int NN> __device__ __forceinline__ void cp_wait() {
    asm volatile("cp.async.wait_group %0;\n" :: "n"(NN));
}
__device__ __forceinline__ void ldsm_x4(uint32_t* r, uint32_t addr) {
    asm volatile("ldmatrix.sync.aligned.m8n8.x4.shared.b16 {%0,%1,%2,%3}, [%4];"
                 : "=r"(r[0]), "=r"(r[1]), "=r"(r[2]), "=r"(r[3]) : "r"(addr));
}
__device__ __forceinline__ void mma_f16(float c[4], uint32_t a0, uint32_t a1, uint32_t a2,
                                        uint32_t a3, uint32_t b0, uint32_t b1) {
    asm volatile(
        "mma.sync.aligned.m16n8k16.row.col.f32.f16.f16.f32 "
        "{%0,%1,%2,%3},{%4,%5,%6,%7},{%8,%9},{%0,%1,%2,%3};\n"
        : "+f"(c[0]), "+f"(c[1]), "+f"(c[2]), "+f"(c[3])
        : "r"(a0), "r"(a1), "r"(a2), "r"(a3), "r"(b0), "r"(b1));
}

// ================= 128x128 fp16 GEMM (attention AV) =================
#define ASZ  (128*72*2)
#define STG  (2*ASZ)
#define HSMEM (2*STG)

template<int EPI, typename OutT>
__global__ void __launch_bounds__(256, 2)
hgemm(const __half* __restrict__ A, const __half* __restrict__ Bm, OutT* __restrict__ C,
      int K, int lda, int ldb, int ldc,
      long sA, long sB, int zdiv, long sC1, long sC2,
      const float* __restrict__ bias, const float* __restrict__ resid)
{
    extern __shared__ char smem[];
    const uint32_t sbase = smem_u32(smem);

    int tid = threadIdx.x;
    int warp = tid >> 5, lane = tid & 31;
    int wm = warp >> 2, wn = warp & 3;
    int z = blockIdx.z;
    const __half* Ab = A + (long)z * sA;
    const __half* Bb = Bm + (long)z * sB;
    long coff = (long)(z / zdiv) * sC1 + (long)(z % zdiv) * sC2;
    OutT* Cb = C + coff;
    int rowBlk = blockIdx.y * 128;
    int colBlk = blockIdx.x * 128;

    float acc[4][4][4];
    #pragma unroll
    for (int mi = 0; mi < 4; mi++)
        #pragma unroll
        for (int ni = 0; ni < 4; ni++)
            #pragma unroll
            for (int r = 0; r < 4; r++) acc[mi][ni][r] = 0.0f;

    uint32_t aoff = (uint32_t)(((wm*64 + (lane & 15)) * 72 + ((lane >> 4) << 3)) * 2);
    uint32_t boff0 = (uint32_t)(((wn*32 + (lane & 7) + ((lane >> 4) << 3)) * 72 + (lane & 8)) * 2);
    uint32_t boff1 = boff0 + 16u*144u;

    auto load_chunk = [&](int ck, int s) {
        uint32_t ab = sbase + s*STG;
        uint32_t bb = ab + ASZ;
        const __half* Ag = Ab + (long)rowBlk * lda + ck*64;
        const __half* Bg = Bb + (long)colBlk * ldb + ck*64;
        #pragma unroll
        for (int it = 0; it < 4; it++) {
            int idx = tid + it*256;
            int row = idx >> 3, gq = idx & 7;
            cpa16(ab + row*144 + gq*16, Ag + (long)row*lda + gq*8);
        }
        #pragma unroll
        for (int it = 0; it < 4; it++) {
            int idx = tid + it*256;
            int row = idx >> 3, gq = idx & 7;
            cpa16(bb + row*144 + gq*16, Bg + (long)row*ldb + gq*8);
        }
        cp_commit();
    };

    int nc = K >> 6;
    load_chunk(0, 0);

    for (int c = 0; c < nc; c++) {
        int s = c & 1;
        if (c + 1 < nc) { load_chunk(c + 1, s ^ 1); cp_wait<1>(); }
        else            { cp_wait<0>(); }
        __syncthreads();

        uint32_t As = sbase + s*STG;
        uint32_t Bs = As + ASZ;
        #pragma unroll
        for (int kk = 0; kk < 64; kk += 16) {
            uint32_t a[4][4], b[2][4];
            #pragma unroll
            for (int mi = 0; mi < 4; mi++)
                ldsm_x4(a[mi], As + aoff + mi*2304u + kk*2);
            ldsm_x4(b[0], Bs + boff0 + kk*2);
            ldsm_x4(b[1], Bs + boff1 + kk*2);
            #pragma unroll
            for (int mi = 0; mi < 4; mi++)
                #pragma unroll
                for (int ni = 0; ni < 4; ni++)
                    mma_f16(acc[mi][ni], a[mi][0], a[mi][1], a[mi][2], a[mi][3],
                            b[ni >> 1][(ni & 1)*2], b[ni >> 1][(ni & 1)*2 + 1]);
        }
        __syncthreads();
    }

    int g = lane >> 2, t4 = lane & 3;
    #pragma unroll
    for (int mi = 0; mi < 4; mi++) {
        #pragma unroll
        for (int ni = 0; ni < 4; ni++) {
            int r0 = rowBlk + wm*64 + mi*16 + g;
            int c0 = colBlk + wn*32 + ni*8 + 2*t4;
            float v0 = acc[mi][ni][0], v1 = acc[mi][ni][1];
            float v2 = acc[mi][ni][2], v3 = acc[mi][ni][3];
            if (EPI >= 2) {
                float b0 = bias[c0], b1 = bias[c0+1];
                v0 += b0; v1 += b1; v2 += b0; v3 += b1;
            }
            if (EPI == 2) {
                v0 = gelu_exact(v0); v1 = gelu_exact(v1);
                v2 = gelu_exact(v2); v3 = gelu_exact(v3);
            }
            if (EPI == 3) {
                const float2 ra = *(const float2*)&resid[coff + (long)r0*ldc + c0];
                const float2 rb = *(const float2*)&resid[coff + (long)(r0+8)*ldc + c0];
                v0 += ra.x; v1 += ra.y; v2 += rb.x; v3 += rb.y;
            }
            if (EPI == 0 || EPI == 2) {
                *(__half2*)&((__half*)Cb)[(long)r0*ldc + c0]     = __floats2half2_rn(v0, v1);
                *(__half2*)&((__half*)Cb)[(long)(r0+8)*ldc + c0] = __floats2half2_rn(v2, v3);
            } else {
                *(float2*)&((float*)Cb)[(long)r0*ldc + c0]     = make_float2(v0, v1);
                *(float2*)&((float*)Cb)[(long)(r0+8)*ldc + c0] = make_float2(v2, v3);
            }
        }
    }
}

// ================= 128x256 fp16 GEMM, 3-stage pipeline =================
#define A2SZ (128*144)        // bytes per A tile
#define B2SZ (256*144)
#define STG2 (A2SZ + B2SZ)    // 55296
#define SMEM2 (3*STG2)        // 165888

template<int EPI, typename OutT>
__global__ void __launch_bounds__(256, 1)
hgemm256(const __half* __restrict__ A, const __half* __restrict__ Bm, OutT* __restrict__ C,
         int K, int lda, int ldb, int ldc,
         long sA, long sB, int zdiv, long sC1, long sC2,
         const float* __restrict__ bias, const float* __restrict__ resid)
{
    extern __shared__ char smem[];
    const uint32_t sbase = smem_u32(smem);

    int tid = threadIdx.x;
    int warp = tid >> 5, lane = tid & 31;
    int wm = warp >> 2, wn = warp & 3;     // 2x4 warp grid, 64x64 warp tile
    int z = blockIdx.z;
    const __half* Ab = A + (long)z * sA;
    const __half* Bb = Bm + (long)z * sB;
    long coff = (long)(z / zdiv) * sC1 + (long)(z % zdiv) * sC2;
    OutT* Cb = C + coff;
    int rowBlk = blockIdx.y * 128;
    int colBlk = blockIdx.x * 256;

    float acc[4][8][4];
    #pragma unroll
    for (int mi = 0; mi < 4; mi++)
        #pragma unroll
        for (int ni = 0; ni < 8; ni++)
            #pragma unroll
            for (int r = 0; r < 4; r++) acc[mi][ni][r] = 0.0f;

    uint32_t aoff = (uint32_t)(((wm*64 + (lane & 15)) * 72 + ((lane >> 4) << 3)) * 2);
    uint32_t boff = (uint32_t)(((wn*64 + (lane & 7) + ((lane >> 4) << 3)) * 72 + (lane & 8)) * 2);

    auto load_chunk = [&](int ck, int s) {
        uint32_t ab = sbase + s*STG2;
        uint32_t bb = ab + A2SZ;
        const __half* Ag = Ab + (long)rowBlk * lda + ck*64;
        const __half* Bg = Bb + (long)colBlk * ldb + ck*64;
        #pragma unroll
        for (int it = 0; it < 4; it++) {
            int idx = tid + it*256;
            int row = idx >> 3, gq = idx & 7;
            cpa16(ab + row*144 + gq*16, Ag + (long)row*lda + gq*8);
        }
        #pragma unroll
        for (int it = 0; it < 8; it++) {
            int idx = tid + it*256;
            int row = idx >> 3, gq = idx & 7;
            cpa16(bb + row*144 + gq*16, Bg + (long)row*ldb + gq*8);
        }
        cp_commit();
    };

    int nc = K >> 6;
    load_chunk(0, 0);
    if (nc > 1) load_chunk(1, 1);

    for (int c = 0; c < nc; c++) {
        int s = c % 3;
        if (c + 1 < nc) cp_wait<1>(); else cp_wait<0>();
        __syncthreads();
        if (c + 2 < nc) load_chunk(c + 2, (c + 2) % 3);

        uint32_t As = sbase + s*STG2;
        uint32_t Bs = As + A2SZ;
        #pragma unroll
        for (int kk = 0; kk < 64; kk += 16) {
            uint32_t a[4][4], b[4][4];
            #pragma unroll
            for (int mi = 0; mi < 4; mi++)
                ldsm_x4(a[mi], As + aoff + mi*2304u + kk*2);
            #pragma unroll
            for (int j = 0; j < 4; j++)
                ldsm_x4(b[j], Bs + boff + j*2304u + kk*2);
            #pragma unroll
            for (int mi = 0; mi < 4; mi++)
                #pragma unroll
                for (int ni = 0; ni < 8; ni++)
                    mma_f16(acc[mi][ni], a[mi][0], a[mi][1], a[mi][2], a[mi][3],
                            b[ni >> 1][(ni & 1)*2], b[ni >> 1][(ni & 1)*2 + 1]);
        }
    }

    __syncthreads();
    int g = lane >> 2, t4 = lane & 3;
    #pragma unroll
    for (int mi = 0; mi < 4; mi++) {
        #pragma unroll
        for (int ni = 0; ni < 8; ni++) {
            int r0 = rowBlk + wm*64 + mi*16 + g;
            int c0 = colBlk + wn*64 + ni*8 + 2*t4;
            float v0 = acc[mi][ni][0], v1 = acc[mi][ni][1];
            float v2 = acc[mi][ni][2], v3 = acc[mi][ni][3];
            if (EPI >= 2) {
                float b0 = bias[c0], b1 = bias[c0+1];
                v0 += b0; v1 += b1; v2 += b0; v3 += b1;
            }
            if (EPI == 2) {
                v0 = gelu_exact(v0); v1 = gelu_exact(v1);
                v2 = gelu_exact(v2); v3 = gelu_exact(v3);
            }
            if (EPI == 3) {
                const float2 ra = *(const float2*)&resid[coff + (long)r0*ldc + c0];
                const float2 rb = *(const float2*)&resid[coff + (long)(r0+8)*ldc + c0];
                v0 += ra.x; v1 += ra.y; v2 += rb.x; v3 += rb.y;
            }
            if (EPI == 0 || EPI == 2) {
                *(__half2*)&((__half*)Cb)[(long)r0*ldc + c0]     = __floats2half2_rn(v0, v1);
                *(__half2*)&((__half*)Cb)[(long)(r0+8)*ldc + c0] = __floats2half2_rn(v2, v3);
            } else {
                *(float2*)&((float*)Cb)[(long)r0*ldc + c0]     = make_float2(v0, v1);
                *(float2*)&((float*)Cb)[(long)(r0+8)*ldc + c0] = make_float2(v2, v3);
            }
        }
    }
}

// ---------------- transpose fp32 -> fp16 ----------------
__global__ void transpose_h(const float* __restrict__ src, __half* __restrict__ dst,
                            int R, int Ccol)
{
    __shared__ float t[32][33];
    int c0 = blockIdx.x * 32, r0 = blockIdx.y * 32;
    int x = c0 + threadIdx.x;
    #pragma unroll
    for (int j = threadIdx.y; j < 32; j += 8)
        t[j][threadIdx.x] = src[(long)(r0 + j) * Ccol + x];
    __syncthreads();
    int x2 = r0 + threadIdx.x;
    #pragma unroll
    for (int j = threadIdx.y; j < 32; j += 8)
        dst[(long)(c0 + j) * R + x2] = __float2half_rn(t[threadIdx.x][j]);
}

// ---------------- conv (one of q/k/vt per kernel) ----------------
// MODE 0 -> g_hq, 1 -> g_hk, 2 -> g_hvt (transposed)
template<int MODE>
__global__ void __launch_bounds__(256) conv_one(const float* __restrict__ x,
                                               const float* __restrict__ w)
{
    __shared__ float sp[3][P_+2][P_+2];
    __shared__ float sw[81];
    int tid = threadIdx.x;
    int patch = blockIdx.x;
    int b = patch >> 8;
    int n = patch & 255;
    const float* xp = x + (long)patch * C_;

    if (tid < 81) sw[tid] = w[tid];
    for (int i = tid; i < 3*(P_+2)*(P_+2); i += 256)
        ((float*)sp)[i] = 0.0f;
    __syncthreads();
    for (int i = tid; i < C_; i += 256) {
        int ch = i >> 10;
        int s  = i & 1023;
        sp[ch][(s >> 5)+1][(s & 31)+1] = xp[i];
    }
    __syncthreads();

    #pragma unroll
    for (int pos = tid; pos < 1024; pos += 256) {
        int yy = pos >> 5, xx = pos & 31;
        float a0 = 0.f, a1 = 0.f, a2 = 0.f;
        #pragma unroll
        for (int i = 0; i < 3; i++)
            #pragma unroll
            for (int dy = 0; dy < 3; dy++)
                #pragma unroll
                for (int dx = 0; dx < 3; dx++) {
                    float val = sp[i][yy+dy][xx+dx];
                    int wi = i*9 + dy*3 + dx;
                    a0 = fmaf(val, sw[wi],      a0);
                    a1 = fmaf(val, sw[27 + wi], a1);
                    a2 = fmaf(val, sw[54 + wi], a2);
                }
        float av[3] = {a0, a1, a2};
        #pragma unroll
        for (int o = 0; o < 3; o++) {
            int c = o*1024 + pos;
            int h = c / HD_;
            int d = c - h*HD_;
            long bh = (long)(b*H_ + h);
            __half hv = __float2half_rn(av[o]);
            if (MODE == 0)      g_hq[(bh*N_ + n)*HD_ + d] = hv;
            else if (MODE == 1) g_hk[(bh*N_ + n)*HD_ + d] = hv;
            else                g_hvt[(bh*HD_ + d)*N_ + n] = hv;
        }
    }
}

// ---------------- softmax over rows of length 256 ----------------
__global__ void softmax256(float* __restrict__ attn, float scale)
{
    __shared__ float red[8];
    long row = blockIdx.x;
    float* p = attn + row * 256;
    int tid = threadIdx.x;
    float v = p[tid] * scale;
    float m = v;
    #pragma unroll
    for (int o = 16; o > 0; o >>= 1) m = fmaxf(m, __shfl_xor_sync(0xffffffffu, m, o));
    if ((tid & 31) == 0) red[tid >> 5] = m;
    __syncthreads();
    float bm = red[0];
    #pragma unroll
    for (int i = 1; i < 8; i++) bm = fmaxf(bm, red[i]);
    float e = __expf(v - bm);
    float s = e;
    #pragma unroll
    for (int o = 16; o > 0; o >>= 1) s += __shfl_xor_sync(0xffffffffu, s, o);
    __syncthreads();
    if ((tid & 31) == 0) red[tid >> 5] = s;
    __syncthreads();
    float bs = 0.0f;
    #pragma unroll
    for (int i = 0; i < 8; i++) bs += red[i];
    p[tid] = e / bs;
}

// ---------------- re-attention (head mix + BN) -> fp16 ----------------
__global__ void reatten_kernel(const float* __restrict__ w,  const float* __restrict__ rb,
                               const float* __restrict__ g,  const float* __restrict__ bta,
                               const float* __restrict__ mean, const float* __restrict__ var)
{
    __shared__ float sw[64], sscale[8], sshift[8];
    int tid = threadIdx.x;
    if (tid < 64) sw[tid] = w[tid];
    if (tid < 8) {
        float inv = rsqrtf(var[tid] + 1e-5f);
        float gi = g[tid] * inv;
        sscale[tid] = gi;
        sshift[tid] = bta[tid] + (rb[tid] - mean[tid]) * gi;
    }
    __syncthreads();
    long idx = (long)blockIdx.x * blockDim.x + tid;
    int b  = (int)(idx >> 16);
    int nm = (int)(idx & 65535);
    const float* base = g_attn + ((long)b * H_) * 65536 + nm;
    float in[8];
    #pragma unroll
    for (int i = 0; i < 8; i++) in[i] = base[(long)i * 65536];
    __half* obase = g_hattn2 + ((long)b * H_) * 65536 + nm;
    #pragma unroll
    for (int o = 0; o < 8; o++) {
        float s = 0.0f;
        #pragma unroll
        for (int i = 0; i < 8; i++) s = fmaf(sw[o*8 + i], in[i], s);
        obase[(long)o * 65536] = __float2half_rn(s * sscale[o] + sshift[o]);
    }
}

// ---------------- LayerNorm: two-level stats ----------------
__global__ void ln_part(const float* __restrict__ y)
{
    __shared__ double rs[8], rq[8];
    int b = blockIdx.y, seg = blockIdx.x;
    const float* p = y + (long)b * NC_ + (long)seg * (NC_/32);
    double s = 0.0, q = 0.0;
    for (int i = threadIdx.x; i < NC_/32; i += 256) {
        double v = (double)p[i];
        s += v; q += v * v;
    }
    #pragma unroll
    for (int o = 16; o > 0; o >>= 1) {
        s += __shfl_xor_sync(0xffffffffu, s, o);
        q += __shfl_xor_sync(0xffffffffu, q, o);
    }
    int lane = threadIdx.x & 31, wid = threadIdx.x >> 5;
    if (lane == 0) { rs[wid] = s; rq[wid] = q; }
    __syncthreads();
    if (threadIdx.x == 0) {
        double S = 0.0, Q = 0.0;
        #pragma unroll
        for (int i = 0; i < 8; i++) { S += rs[i]; Q += rq[i]; }
        g_part[(b*32 + seg)*2]     = S;
        g_part[(b*32 + seg)*2 + 1] = Q;
    }
}

__global__ void ln_fin(float* __restrict__ stats)
{
    int b = blockIdx.x, t = threadIdx.x;
    double s = g_part[(b*32 + t)*2];
    double q = g_part[(b*32 + t)*2 + 1];
    #pragma unroll
    for (int o = 16; o > 0; o >>= 1) {
        s += __shfl_xor_sync(0xffffffffu, s, o);
        q += __shfl_xor_sync(0xffffffffu, q, o);
    }
    if (t == 0) {
        double mu  = s / (double)NC_;
        double var = q / (double)NC_ - mu * mu;
        stats[b*2]   = (float)mu;
        stats[b*2+1] = (float)rsqrt(var + 1e-5);
    }
}

__global__ void ln_apply_dual(const float* __restrict__ y, const float* __restrict__ stats,
                              const float* __restrict__ g, const float* __restrict__ beta,
                              float* __restrict__ outf, __half* __restrict__ outh)
{
    long i = (long)blockIdx.x * blockDim.x + threadIdx.x;
    int b = (int)(i / NC_);
    int r = (int)(i % NC_);
    float v = (y[i] - stats[b*2]) * stats[b*2+1] * g[r] + beta[r];
    outf[i] = v;
    outh[i] = __float2half_rn(v);
}

__global__ void ln_apply(const float* __restrict__ y, const float* __restrict__ stats,
                         const float* __restrict__ g, const float* __restrict__ beta,
                         float* __restrict__ out)
{
    long i = (long)blockIdx.x * blockDim.x + threadIdx.x;
    int b = (int)(i / NC_);
    int r = (int)(i % NC_);
    out[i] = (y[i] - stats[b*2]) * stats[b*2+1] * g[r] + beta[r];
}

// ---------------- launch ----------------
extern "C" void kernel_launch(void* const* d_in, const int* in_sizes, int n_in,
                              void* d_out, int out_size)
{
    const float* x        = (const float*)d_in[0];
    const float* qconv_w  = (const float*)d_in[1];
    const float* kconv_w  = (const float*)d_in[2];
    const float* vconv_w  = (const float*)d_in[3];
    const float* reat_w   = (const float*)d_in[4];
    const float* reat_b   = (const float*)d_in[5];
    const float* bn_gamma = (const float*)d_in[6];
    const float* bn_beta  = (const float*)d_in[7];
    const float* bn_mean  = (const float*)d_in[8];
    const float* bn_var   = (const float*)d_in[9];
    const float* proj_w   = (const float*)d_in[10];
    const float* proj_b   = (const float*)d_in[11];
    const float* ln_g     = (const float*)d_in[12];
    const float* ln_b     = (const float*)d_in[13];
    const float* ff_w1    = (const float*)d_in[14];
    const float* ff_b1    = (const float*)d_in[15];
    const float* ff_w2    = (const float*)d_in[16];
    const float* ff_b2    = (const float*)d_in[17];
    float* out = (float*)d_out;

    __half *pq, *pk, *pvt, *pattn2, *pctx, *pynh, *ph, *pprojT, *pw1T, *pw2T;
    float *pattn, *py1, *pyn, *py2, *pstats;
    cudaGetSymbolAddress((void**)&pq,     g_hq);
    cudaGetSymbolAddress((void**)&pk,     g_hk);
    cudaGetSymbolAddress((void**)&pvt,    g_hvt);
    cudaGetSymbolAddress((void**)&pattn2, g_hattn2);
    cudaGetSymbolAddress((void**)&pctx,   g_hctx);
    cudaGetSymbolAddress((void**)&pynh,   g_hynh);
    cudaGetSymbolAddress((void**)&ph,     g_hh);
    cudaGetSymbolAddress((void**)&pprojT, g_hprojT);
    cudaGetSymbolAddress((void**)&pw1T,   g_hw1T);
    cudaGetSymbolAddress((void**)&pw2T,   g_hw2T);
    cudaGetSymbolAddress((void**)&pattn,  g_attn);
    cudaGetSymbolAddress((void**)&py1,    g_y1);
    cudaGetSymbolAddress((void**)&pyn,    g_yn);
    cudaGetSymbolAddress((void**)&py2,    g_y2);
    cudaGetSymbolAddress((void**)&pstats, g_stats);

    cudaFuncSetAttribute(hgemm<0,__half>,    cudaFuncAttributeMaxDynamicSharedMemorySize, HSMEM);
    cudaFuncSetAttribute(hgemm256<1,float>,  cudaFuncAttributeMaxDynamicSharedMemorySize, SMEM2);
    cudaFuncSetAttribute(hgemm256<2,__half>, cudaFuncAttributeMaxDynamicSharedMemorySize, SMEM2);
    cudaFuncSetAttribute(hgemm256<3,float>,  cudaFuncAttributeMaxDynamicSharedMemorySize, SMEM2);

    // 0. weight transposes (fp32 -> fp16, B layout [n][k])
    {
        dim3 blk(32, 8);
        transpose_h<<<dim3(C_/32, C_/32), blk>>>(proj_w, pprojT, C_, C_);
        transpose_h<<<dim3(FF_/32, C_/32), blk>>>(ff_w1, pw1T, C_, FF_);
        transpose_h<<<dim3(C_/32, FF_/32), blk>>>(ff_w2, pw2T, FF_, C_);
    }

    // 1. conv QKV (split, low regs)
    conv_one<0><<<B_*N_, 256>>>(x, qconv_w);
    conv_one<1><<<B_*N_, 256>>>(x, kconv_w);
    conv_one<2><<<B_*N_, 256>>>(x, vconv_w);

    // 2. S = Q K^T  (per bh: 256x256x384) -> fp32 attn (128x256 tiles)
    hgemm256<1,float><<<dim3(1,2,BH_), 256, SMEM2>>>(pq, pk, pattn,
        HD_, HD_, HD_, N_, (long)N_*HD_, (long)N_*HD_, 1, 65536L, 0L, nullptr, nullptr);

    // 3. softmax
    softmax256<<<BH_*N_, 256>>>(pattn, 0.051031036307982884f);

    // 4. re-attention head mix + BN -> fp16 attn2
    reatten_kernel<<<(B_*65536)/256, 256>>>(reat_w, reat_b, bn_gamma, bn_beta, bn_mean, bn_var);

    // 5. ctx = attn2 @ V  (per bh: 256x384x256) -> fp16 (B,N,C)
    hgemm<0,__half><<<dim3(3,2,BH_), 256, HSMEM>>>(pattn2, pvt, pctx,
        N_, N_, N_, C_, 65536L, (long)HD_*N_, H_, (long)N_*C_, (long)HD_, nullptr, nullptr);

    // 6. y1 = x + ctx @ proj_w + proj_b
    hgemm256<3,float><<<dim3(C_/256, (B_*N_)/128, 1), 256, SMEM2>>>(pctx, pprojT, py1,
        C_, C_, C_, C_, 0L, 0L, 1, 0L, 0L, proj_b, x);

    // 7. LN1
    ln_part<<<dim3(32, B_), 256>>>(py1);
    ln_fin<<<B_, 32>>>(pstats);
    ln_apply_dual<<<QKV_SZ/256, 256>>>(py1, pstats, ln_g, ln_b, pyn, pynh);

    // 8. h = gelu(yn @ ff_w1 + b1)
    hgemm256<2,__half><<<dim3(FF_/256, (B_*N_)/128, 1), 256, SMEM2>>>(pynh, pw1T, ph,
        C_, C_, C_, FF_, 0L, 0L, 1, 0L, 0L, ff_b1, nullptr);

    // 9. y2 = yn + h @ ff_w2 + b2
    hgemm256<3,float><<<dim3(C_/256, (B_*N_)/128, 1), 256, SMEM2>>>(ph, pw2T, py2,
        FF_, FF_, FF_, C_, 0L, 0L, 1, 0L, 0L, ff_b2, pyn);

    // 10. LN2 -> out
    ln_part<<<dim3(32, B_), 256>>>(py2);
    ln_fin<<<B_, 32>>>(pstats);
    ln_apply<<<QKV_SZ/256, 256>>>(py2, pstats, ln_g, ln_b, out);
}

// round 6
// speedup vs baseline: 6.7359x; 1.0206x over previous
#include <cuda_runtime.h>
#include <cuda_fp16.h>
#include <math.h>
#include <stdint.h>

// ---------------- problem constants ----------------
#define B_   8
#define N_   256
#define C_   3072
#define H_   8
#define HD_  384
#define FF_  12288
#define P_   32
#define NC_  (N_*C_)
#define BH_  (B_*H_)
#define QKV_SZ   (B_*N_*C_)
#define ATT_SZ   (B_*H_*N_*N_)
#define HBUF_SZ  (B_*N_*FF_)

// ---------------- device scratch ----------------
__device__ __align__(256) __half g_hq[QKV_SZ];
__device__ __align__(256) __half g_hk[QKV_SZ];
__device__ __align__(256) __half g_hvt[QKV_SZ];     // V^T: (BH, hd, N)
__device__ __align__(256) __half g_hattn2[ATT_SZ];
__device__ __align__(256) __half g_hctx[QKV_SZ];
__device__ __align__(256) __half g_hynh[QKV_SZ];
__device__ __align__(256) __half g_hh[HBUF_SZ];
__device__ __align__(256) __half g_hprojT[C_*C_];
__device__ __align__(256) __half g_hw1T[(long)C_*FF_];
__device__ __align__(256) __half g_hw2T[(long)C_*FF_];
__device__ float g_attn[ATT_SZ];
__device__ float g_y1[QKV_SZ];
__device__ float g_yn[QKV_SZ];
__device__ float g_y2[QKV_SZ];
__device__ float g_stats[B_*2];
__device__ double g_part[B_*32*2];

// ---------------- helpers ----------------
__device__ __forceinline__ float gelu_exact(float x) {
    return 0.5f * x * (1.0f + erff(x * 0.70710678118654752f));
}
__device__ __forceinline__ uint32_t smem_u32(const void* p) {
    return (uint32_t)__cvta_generic_to_shared(p);
}
__device__ __forceinline__ void cpa16(uint32_t dst, const void* src) {
    asm volatile("cp.async.cg.shared.global [%0], [%1], 16;\n" :: "r"(dst), "l"(src));
}
__device__ __forceinline__ void cp_commit() { asm volatile("cp.async.commit_group;\n"); }
template<int NN> __device__ __forceinline__ void cp_wait() {
    asm volatile("cp.async.wait_group %0;\n" :: "n"(NN));
}
__device__ __forceinline__ void ldsm_x4(uint32_t* r, uint32_t addr) {
    asm volatile("ldmatrix.sync.aligned.m8n8.x4.shared.b16 {%0,%1,%2,%3}, [%4];"
                 : "=r"(r[0]), "=r"(r[1]), "=r"(r[2]), "=r"(r[3]) : "r"(addr));
}
__device__ __forceinline__ void mma_f16(float c[4], uint32_t a0, uint32_t a1, uint32_t a2,
                                        uint32_t a3, uint32_t b0, uint32_t b1) {
    asm volatile(
        "mma.sync.aligned.m16n8k16.row.col.f32.f16.f16.f32 "
        "{%0,%1,%2,%3},{%4,%5,%6,%7},{%8,%9},{%0,%1,%2,%3};\n"
        : "+f"(c[0]), "+f"(c[1]), "+f"(c[2]), "+f"(c[3])
        : "r"(a0), "r"(a1), "r"(a2), "r"(a3), "r"(b0), "r"(b1));
}

// ================= 128x128 fp16 GEMM (attention AV) =================
#define ASZ  (128*72*2)
#define STG  (2*ASZ)
#define HSMEM (2*STG)

template<int EPI, typename OutT>
__global__ void __launch_bounds__(256, 2)
hgemm(const __half* __restrict__ A, const __half* __restrict__ Bm, OutT* __restrict__ C,
      int K, int lda, int ldb, int ldc,
      long sA, long sB, int zdiv, long sC1, long sC2,
      const float* __restrict__ bias, const float* __restrict__ resid)
{
    extern __shared__ char smem[];
    const uint32_t sbase = smem_u32(smem);

    int tid = threadIdx.x;
    int warp = tid >> 5, lane = tid & 31;
    int wm = warp >> 2, wn = warp & 3;
    int z = blockIdx.z;
    const __half* Ab = A + (long)z * sA;
    const __half* Bb = Bm + (long)z * sB;
    long coff = (long)(z / zdiv) * sC1 + (long)(z % zdiv) * sC2;
    OutT* Cb = C + coff;
    int rowBlk = blockIdx.y * 128;
    int colBlk = blockIdx.x * 128;

    float acc[4][4][4];
    #pragma unroll
    for (int mi = 0; mi < 4; mi++)
        #pragma unroll
        for (int ni = 0; ni < 4; ni++)
            #pragma unroll
            for (int r = 0; r < 4; r++) acc[mi][ni][r] = 0.0f;

    uint32_t aoff = (uint32_t)(((wm*64 + (lane & 15)) * 72 + ((lane >> 4) << 3)) * 2);
    uint32_t boff0 = (uint32_t)(((wn*32 + (lane & 7) + ((lane >> 4) << 3)) * 72 + (lane & 8)) * 2);
    uint32_t boff1 = boff0 + 16u*144u;

    auto load_chunk = [&](int ck, int s) {
        uint32_t ab = sbase + s*STG;
        uint32_t bb = ab + ASZ;
        const __half* Ag = Ab + (long)rowBlk * lda + ck*64;
        const __half* Bg = Bb + (long)colBlk * ldb + ck*64;
        #pragma unroll
        for (int it = 0; it < 4; it++) {
            int idx = tid + it*256;
            int row = idx >> 3, gq = idx & 7;
            cpa16(ab + row*144 + gq*16, Ag + (long)row*lda + gq*8);
        }
        #pragma unroll
        for (int it = 0; it < 4; it++) {
            int idx = tid + it*256;
            int row = idx >> 3, gq = idx & 7;
            cpa16(bb + row*144 + gq*16, Bg + (long)row*ldb + gq*8);
        }
        cp_commit();
    };

    int nc = K >> 6;
    load_chunk(0, 0);

    for (int c = 0; c < nc; c++) {
        int s = c & 1;
        if (c + 1 < nc) { load_chunk(c + 1, s ^ 1); cp_wait<1>(); }
        else            { cp_wait<0>(); }
        __syncthreads();

        uint32_t As = sbase + s*STG;
        uint32_t Bs = As + ASZ;
        #pragma unroll
        for (int kk = 0; kk < 64; kk += 16) {
            uint32_t a[4][4], b[2][4];
            #pragma unroll
            for (int mi = 0; mi < 4; mi++)
                ldsm_x4(a[mi], As + aoff + mi*2304u + kk*2);
            ldsm_x4(b[0], Bs + boff0 + kk*2);
            ldsm_x4(b[1], Bs + boff1 + kk*2);
            #pragma unroll
            for (int mi = 0; mi < 4; mi++)
                #pragma unroll
                for (int ni = 0; ni < 4; ni++)
                    mma_f16(acc[mi][ni], a[mi][0], a[mi][1], a[mi][2], a[mi][3],
                            b[ni >> 1][(ni & 1)*2], b[ni >> 1][(ni & 1)*2 + 1]);
        }
        __syncthreads();
    }

    int g = lane >> 2, t4 = lane & 3;
    #pragma unroll
    for (int mi = 0; mi < 4; mi++) {
        #pragma unroll
        for (int ni = 0; ni < 4; ni++) {
            int r0 = rowBlk + wm*64 + mi*16 + g;
            int c0 = colBlk + wn*32 + ni*8 + 2*t4;
            float v0 = acc[mi][ni][0], v1 = acc[mi][ni][1];
            float v2 = acc[mi][ni][2], v3 = acc[mi][ni][3];
            if (EPI >= 2) {
                float b0 = bias[c0], b1 = bias[c0+1];
                v0 += b0; v1 += b1; v2 += b0; v3 += b1;
            }
            if (EPI == 2) {
                v0 = gelu_exact(v0); v1 = gelu_exact(v1);
                v2 = gelu_exact(v2); v3 = gelu_exact(v3);
            }
            if (EPI == 3) {
                const float2 ra = *(const float2*)&resid[coff + (long)r0*ldc + c0];
                const float2 rb = *(const float2*)&resid[coff + (long)(r0+8)*ldc + c0];
                v0 += ra.x; v1 += ra.y; v2 += rb.x; v3 += rb.y;
            }
            if (EPI == 0 || EPI == 2) {
                *(__half2*)&((__half*)Cb)[(long)r0*ldc + c0]     = __floats2half2_rn(v0, v1);
                *(__half2*)&((__half*)Cb)[(long)(r0+8)*ldc + c0] = __floats2half2_rn(v2, v3);
            } else {
                *(float2*)&((float*)Cb)[(long)r0*ldc + c0]     = make_float2(v0, v1);
                *(float2*)&((float*)Cb)[(long)(r0+8)*ldc + c0] = make_float2(v2, v3);
            }
        }
    }
}

// ================= 128x256 fp16 GEMM, 4-stage pipeline =================
#define A2SZ (128*144)
#define B2SZ (256*144)
#define STG2 (A2SZ + B2SZ)    // 55296
#define SMEM2 (4*STG2)        // 221184

template<int EPI, typename OutT>
__global__ void __launch_bounds__(256, 1)
hgemm256(const __half* __restrict__ A, const __half* __restrict__ Bm, OutT* __restrict__ C,
         int K, int lda, int ldb, int ldc,
         long sA, long sB, int zdiv, long sC1, long sC2,
         const float* __restrict__ bias, const float* __restrict__ resid)
{
    extern __shared__ char smem[];
    const uint32_t sbase = smem_u32(smem);

    int tid = threadIdx.x;
    int warp = tid >> 5, lane = tid & 31;
    int wm = warp >> 2, wn = warp & 3;     // 2x4 warp grid, 64x64 warp tile
    int z = blockIdx.z;
    const __half* Ab = A + (long)z * sA;
    const __half* Bb = Bm + (long)z * sB;
    long coff = (long)(z / zdiv) * sC1 + (long)(z % zdiv) * sC2;
    OutT* Cb = C + coff;
    int rowBlk = blockIdx.y * 128;
    int colBlk = blockIdx.x * 256;

    float acc[4][8][4];
    #pragma unroll
    for (int mi = 0; mi < 4; mi++)
        #pragma unroll
        for (int ni = 0; ni < 8; ni++)
            #pragma unroll
            for (int r = 0; r < 4; r++) acc[mi][ni][r] = 0.0f;

    uint32_t aoff = (uint32_t)(((wm*64 + (lane & 15)) * 72 + ((lane >> 4) << 3)) * 2);
    uint32_t boff = (uint32_t)(((wn*64 + (lane & 7) + ((lane >> 4) << 3)) * 72 + (lane & 8)) * 2);

    auto load_chunk = [&](int ck, int s) {
        uint32_t ab = sbase + s*STG2;
        uint32_t bb = ab + A2SZ;
        const __half* Ag = Ab + (long)rowBlk * lda + ck*64;
        const __half* Bg = Bb + (long)colBlk * ldb + ck*64;
        #pragma unroll
        for (int it = 0; it < 4; it++) {
            int idx = tid + it*256;
            int row = idx >> 3, gq = idx & 7;
            cpa16(ab + row*144 + gq*16, Ag + (long)row*lda + gq*8);
        }
        #pragma unroll
        for (int it = 0; it < 8; it++) {
            int idx = tid + it*256;
            int row = idx >> 3, gq = idx & 7;
            cpa16(bb + row*144 + gq*16, Bg + (long)row*ldb + gq*8);
        }
        cp_commit();
    };

    int nc = K >> 6;
    load_chunk(0, 0);
    if (nc > 1) load_chunk(1, 1); else cp_commit();
    if (nc > 2) load_chunk(2, 2); else cp_commit();

    for (int c = 0; c < nc; c++) {
        cp_wait<2>();
        __syncthreads();
        if (c + 3 < nc) load_chunk(c + 3, (c + 3) & 3);
        else            cp_commit();

        uint32_t As = sbase + (c & 3)*STG2;
        uint32_t Bs = As + A2SZ;
        #pragma unroll
        for (int kk = 0; kk < 64; kk += 16) {
            uint32_t a[4][4], b[4][4];
            #pragma unroll
            for (int mi = 0; mi < 4; mi++)
                ldsm_x4(a[mi], As + aoff + mi*2304u + kk*2);
            #pragma unroll
            for (int j = 0; j < 4; j++)
                ldsm_x4(b[j], Bs + boff + j*2304u + kk*2);
            #pragma unroll
            for (int mi = 0; mi < 4; mi++)
                #pragma unroll
                for (int ni = 0; ni < 8; ni++)
                    mma_f16(acc[mi][ni], a[mi][0], a[mi][1], a[mi][2], a[mi][3],
                            b[ni >> 1][(ni & 1)*2], b[ni >> 1][(ni & 1)*2 + 1]);
        }
    }

    __syncthreads();
    int g = lane >> 2, t4 = lane & 3;
    #pragma unroll
    for (int mi = 0; mi < 4; mi++) {
        #pragma unroll
        for (int ni = 0; ni < 8; ni++) {
            int r0 = rowBlk + wm*64 + mi*16 + g;
            int c0 = colBlk + wn*64 + ni*8 + 2*t4;
            float v0 = acc[mi][ni][0], v1 = acc[mi][ni][1];
            float v2 = acc[mi][ni][2], v3 = acc[mi][ni][3];
            if (EPI >= 2) {
                float b0 = bias[c0], b1 = bias[c0+1];
                v0 += b0; v1 += b1; v2 += b0; v3 += b1;
            }
            if (EPI == 2) {
                v0 = gelu_exact(v0); v1 = gelu_exact(v1);
                v2 = gelu_exact(v2); v3 = gelu_exact(v3);
            }
            if (EPI == 3) {
                const float2 ra = *(const float2*)&resid[coff + (long)r0*ldc + c0];
                const float2 rb = *(const float2*)&resid[coff + (long)(r0+8)*ldc + c0];
                v0 += ra.x; v1 += ra.y; v2 += rb.x; v3 += rb.y;
            }
            if (EPI == 0 || EPI == 2) {
                *(__half2*)&((__half*)Cb)[(long)r0*ldc + c0]     = __floats2half2_rn(v0, v1);
                *(__half2*)&((__half*)Cb)[(long)(r0+8)*ldc + c0] = __floats2half2_rn(v2, v3);
            } else {
                *(float2*)&((float*)Cb)[(long)r0*ldc + c0]     = make_float2(v0, v1);
                *(float2*)&((float*)Cb)[(long)(r0+8)*ldc + c0] = make_float2(v2, v3);
            }
        }
    }
}

// ---------------- transpose fp32 -> fp16 ----------------
__global__ void transpose_h(const float* __restrict__ src, __half* __restrict__ dst,
                            int R, int Ccol)
{
    __shared__ float t[32][33];
    int c0 = blockIdx.x * 32, r0 = blockIdx.y * 32;
    int x = c0 + threadIdx.x;
    #pragma unroll
    for (int j = threadIdx.y; j < 32; j += 8)
        t[j][threadIdx.x] = src[(long)(r0 + j) * Ccol + x];
    __syncthreads();
    int x2 = r0 + threadIdx.x;
    #pragma unroll
    for (int j = threadIdx.y; j < 32; j += 8)
        dst[(long)(c0 + j) * R + x2] = __float2half_rn(t[threadIdx.x][j]);
}

// ---------------- conv (one of q/k/vt per kernel) ----------------
template<int MODE>
__global__ void __launch_bounds__(256, 4) conv_one(const float* __restrict__ x,
                                                   const float* __restrict__ w)
{
    __shared__ float sp[3][P_+2][P_+2];
    __shared__ float sw[81];
    int tid = threadIdx.x;
    int patch = blockIdx.x;
    int b = patch >> 8;
    int n = patch & 255;
    const float* xp = x + (long)patch * C_;

    if (tid < 81) sw[tid] = w[tid];
    for (int i = tid; i < 3*(P_+2)*(P_+2); i += 256)
        ((float*)sp)[i] = 0.0f;
    __syncthreads();
    for (int i = tid; i < C_; i += 256) {
        int ch = i >> 10;
        int s  = i & 1023;
        sp[ch][(s >> 5)+1][(s & 31)+1] = xp[i];
    }
    __syncthreads();

    for (int pos = tid; pos < 1024; pos += 256) {
        int yy = pos >> 5, xx = pos & 31;
        float a0 = 0.f, a1 = 0.f, a2 = 0.f;
        #pragma unroll
        for (int i = 0; i < 3; i++)
            #pragma unroll
            for (int dy = 0; dy < 3; dy++)
                #pragma unroll
                for (int dx = 0; dx < 3; dx++) {
                    float val = sp[i][yy+dy][xx+dx];
                    int wi = i*9 + dy*3 + dx;
                    a0 = fmaf(val, sw[wi],      a0);
                    a1 = fmaf(val, sw[27 + wi], a1);
                    a2 = fmaf(val, sw[54 + wi], a2);
                }
        float av[3] = {a0, a1, a2};
        #pragma unroll
        for (int o = 0; o < 3; o++) {
            int c = o*1024 + pos;
            int h = c / HD_;
            int d = c - h*HD_;
            long bh = (long)(b*H_ + h);
            __half hv = __float2half_rn(av[o]);
            if (MODE == 0)      g_hq[(bh*N_ + n)*HD_ + d] = hv;
            else if (MODE == 1) g_hk[(bh*N_ + n)*HD_ + d] = hv;
            else                g_hvt[(bh*HD_ + d)*N_ + n] = hv;
        }
    }
}

// ---------------- fused softmax + re-attention + BN -> fp16 ----------------
// one block per (b, n): warp h = softmax of attn[b,h,n,:]; then head mix.
__global__ void __launch_bounds__(256) softmax_reatten(
    const float* __restrict__ attn, __half* __restrict__ attn2,
    const float* __restrict__ w,  const float* __restrict__ rb,
    const float* __restrict__ g,  const float* __restrict__ bta,
    const float* __restrict__ mean, const float* __restrict__ var)
{
    __shared__ float sp[8][256];
    __shared__ float sw[64], sscale[8], sshift[8];
    int tid = threadIdx.x;
    int h = tid >> 5, lane = tid & 31;
    if (tid < 64) sw[tid] = w[tid];
    if (tid < 8) {
        float inv = rsqrtf(var[tid] + 1e-5f);
        float gi = g[tid] * inv;
        sscale[tid] = gi;
        sshift[tid] = bta[tid] + (rb[tid] - mean[tid]) * gi;
    }
    int b = blockIdx.x >> 8, n = blockIdx.x & 255;
    const float scale = 0.051031036307982884f;
    const float* row = attn + (((long)(b*H_ + h))*N_ + n)*N_;

    float v[8];
    #pragma unroll
    for (int j = 0; j < 8; j++) v[j] = row[lane + j*32] * scale;
    float m = v[0];
    #pragma unroll
    for (int j = 1; j < 8; j++) m = fmaxf(m, v[j]);
    #pragma unroll
    for (int o = 16; o > 0; o >>= 1) m = fmaxf(m, __shfl_xor_sync(0xffffffffu, m, o));
    float s = 0.0f;
    float e[8];
    #pragma unroll
    for (int j = 0; j < 8; j++) { e[j] = __expf(v[j] - m); s += e[j]; }
    #pragma unroll
    for (int o = 16; o > 0; o >>= 1) s += __shfl_xor_sync(0xffffffffu, s, o);
    float inv = 1.0f / s;
    #pragma unroll
    for (int j = 0; j < 8; j++) sp[h][lane + j*32] = e[j] * inv;
    __syncthreads();

    float in[8];
    #pragma unroll
    for (int i = 0; i < 8; i++) in[i] = sp[i][tid];
    #pragma unroll
    for (int o = 0; o < 8; o++) {
        float acc = 0.0f;
        #pragma unroll
        for (int i = 0; i < 8; i++) acc = fmaf(sw[o*8 + i], in[i], acc);
        attn2[(((long)(b*H_ + o))*N_ + n)*N_ + tid] =
            __float2half_rn(acc * sscale[o] + sshift[o]);
    }
}

// ---------------- LayerNorm: two-level stats ----------------
__global__ void ln_part(const float* __restrict__ y)
{
    __shared__ double rs[8], rq[8];
    int b = blockIdx.y, seg = blockIdx.x;
    const float* p = y + (long)b * NC_ + (long)seg * (NC_/32);
    double s = 0.0, q = 0.0;
    for (int i = threadIdx.x; i < NC_/32; i += 256) {
        double v = (double)p[i];
        s += v; q += v * v;
    }
    #pragma unroll
    for (int o = 16; o > 0; o >>= 1) {
        s += __shfl_xor_sync(0xffffffffu, s, o);
        q += __shfl_xor_sync(0xffffffffu, q, o);
    }
    int lane = threadIdx.x & 31, wid = threadIdx.x >> 5;
    if (lane == 0) { rs[wid] = s; rq[wid] = q; }
    __syncthreads();
    if (threadIdx.x == 0) {
        double S = 0.0, Q = 0.0;
        #pragma unroll
        for (int i = 0; i < 8; i++) { S += rs[i]; Q += rq[i]; }
        g_part[(b*32 + seg)*2]     = S;
        g_part[(b*32 + seg)*2 + 1] = Q;
    }
}

__global__ void ln_fin(float* __restrict__ stats)
{
    int b = blockIdx.x, t = threadIdx.x;
    double s = g_part[(b*32 + t)*2];
    double q = g_part[(b*32 + t)*2 + 1];
    #pragma unroll
    for (int o = 16; o > 0; o >>= 1) {
        s += __shfl_xor_sync(0xffffffffu, s, o);
        q += __shfl_xor_sync(0xffffffffu, q, o);
    }
    if (t == 0) {
        double mu  = s / (double)NC_;
        double var = q / (double)NC_ - mu * mu;
        stats[b*2]   = (float)mu;
        stats[b*2+1] = (float)rsqrt(var + 1e-5);
    }
}

__global__ void ln_apply_dual(const float* __restrict__ y, const float* __restrict__ stats,
                              const float* __restrict__ g, const float* __restrict__ beta,
                              float* __restrict__ outf, __half* __restrict__ outh)
{
    long i = (long)blockIdx.x * blockDim.x + threadIdx.x;
    int b = (int)(i / NC_);
    int r = (int)(i % NC_);
    float v = (y[i] - stats[b*2]) * stats[b*2+1] * g[r] + beta[r];
    outf[i] = v;
    outh[i] = __float2half_rn(v);
}

__global__ void ln_apply(const float* __restrict__ y, const float* __restrict__ stats,
                         const float* __restrict__ g, const float* __restrict__ beta,
                         float* __restrict__ out)
{
    long i = (long)blockIdx.x * blockDim.x + threadIdx.x;
    int b = (int)(i / NC_);
    int r = (int)(i % NC_);
    out[i] = (y[i] - stats[b*2]) * stats[b*2+1] * g[r] + beta[r];
}

// ---------------- launch ----------------
extern "C" void kernel_launch(void* const* d_in, const int* in_sizes, int n_in,
                              void* d_out, int out_size)
{
    const float* x        = (const float*)d_in[0];
    const float* qconv_w  = (const float*)d_in[1];
    const float* kconv_w  = (const float*)d_in[2];
    const float* vconv_w  = (const float*)d_in[3];
    const float* reat_w   = (const float*)d_in[4];
    const float* reat_b   = (const float*)d_in[5];
    const float* bn_gamma = (const float*)d_in[6];
    const float* bn_beta  = (const float*)d_in[7];
    const float* bn_mean  = (const float*)d_in[8];
    const float* bn_var   = (const float*)d_in[9];
    const float* proj_w   = (const float*)d_in[10];
    const float* proj_b   = (const float*)d_in[11];
    const float* ln_g     = (const float*)d_in[12];
    const float* ln_b     = (const float*)d_in[13];
    const float* ff_w1    = (const float*)d_in[14];
    const float* ff_b1    = (const float*)d_in[15];
    const float* ff_w2    = (const float*)d_in[16];
    const float* ff_b2    = (const float*)d_in[17];
    float* out = (float*)d_out;

    __half *pq, *pk, *pvt, *pattn2, *pctx, *pynh, *ph, *pprojT, *pw1T, *pw2T;
    float *pattn, *py1, *pyn, *py2, *pstats;
    cudaGetSymbolAddress((void**)&pq,     g_hq);
    cudaGetSymbolAddress((void**)&pk,     g_hk);
    cudaGetSymbolAddress((void**)&pvt,    g_hvt);
    cudaGetSymbolAddress((void**)&pattn2, g_hattn2);
    cudaGetSymbolAddress((void**)&pctx,   g_hctx);
    cudaGetSymbolAddress((void**)&pynh,   g_hynh);
    cudaGetSymbolAddress((void**)&ph,     g_hh);
    cudaGetSymbolAddress((void**)&pprojT, g_hprojT);
    cudaGetSymbolAddress((void**)&pw1T,   g_hw1T);
    cudaGetSymbolAddress((void**)&pw2T,   g_hw2T);
    cudaGetSymbolAddress((void**)&pattn,  g_attn);
    cudaGetSymbolAddress((void**)&py1,    g_y1);
    cudaGetSymbolAddress((void**)&pyn,    g_yn);
    cudaGetSymbolAddress((void**)&py2,    g_y2);
    cudaGetSymbolAddress((void**)&pstats, g_stats);

    cudaFuncSetAttribute(hgemm<0,__half>,    cudaFuncAttributeMaxDynamicSharedMemorySize, HSMEM);
    cudaFuncSetAttribute(hgemm256<1,float>,  cudaFuncAttributeMaxDynamicSharedMemorySize, SMEM2);
    cudaFuncSetAttribute(hgemm256<2,__half>, cudaFuncAttributeMaxDynamicSharedMemorySize, SMEM2);
    cudaFuncSetAttribute(hgemm256<3,float>,  cudaFuncAttributeMaxDynamicSharedMemorySize, SMEM2);

    // 0. weight transposes (fp32 -> fp16, B layout [n][k])
    {
        dim3 blk(32, 8);
        transpose_h<<<dim3(C_/32, C_/32), blk>>>(proj_w, pprojT, C_, C_);
        transpose_h<<<dim3(FF_/32, C_/32), blk>>>(ff_w1, pw1T, C_, FF_);
        transpose_h<<<dim3(C_/32, FF_/32), blk>>>(ff_w2, pw2T, FF_, C_);
    }

    // 1. conv QKV (split, reg-capped)
    conv_one<0><<<B_*N_, 256>>>(x, qconv_w);
    conv_one<1><<<B_*N_, 256>>>(x, kconv_w);
    conv_one<2><<<B_*N_, 256>>>(x, vconv_w);

    // 2. S = Q K^T  (per bh: 256x256x384) -> fp32 attn
    hgemm256<1,float><<<dim3(1,2,BH_), 256, SMEM2>>>(pq, pk, pattn,
        HD_, HD_, HD_, N_, (long)N_*HD_, (long)N_*HD_, 1, 65536L, 0L, nullptr, nullptr);

    // 3+4. fused softmax + re-attention + BN -> fp16 attn2
    softmax_reatten<<<B_*N_, 256>>>(pattn, pattn2, reat_w, reat_b,
                                    bn_gamma, bn_beta, bn_mean, bn_var);

    // 5. ctx = attn2 @ V  (per bh: 256x384x256) -> fp16 (B,N,C)
    hgemm<0,__half><<<dim3(3,2,BH_), 256, HSMEM>>>(pattn2, pvt, pctx,
        N_, N_, N_, C_, 65536L, (long)HD_*N_, H_, (long)N_*C_, (long)HD_, nullptr, nullptr);

    // 6. y1 = x + ctx @ proj_w + proj_b
    hgemm256<3,float><<<dim3(C_/256, (B_*N_)/128, 1), 256, SMEM2>>>(pctx, pprojT, py1,
        C_, C_, C_, C_, 0L, 0L, 1, 0L, 0L, proj_b, x);

    // 7. LN1
    ln_part<<<dim3(32, B_), 256>>>(py1);
    ln_fin<<<B_, 32>>>(pstats);
    ln_apply_dual<<<QKV_SZ/256, 256>>>(py1, pstats, ln_g, ln_b, pyn, pynh);

    // 8. h = gelu(yn @ ff_w1 + b1)
    hgemm256<2,__half><<<dim3(FF_/256, (B_*N_)/128, 1), 256, SMEM2>>>(pynh, pw1T, ph,
        C_, C_, C_, FF_, 0L, 0L, 1, 0L, 0L, ff_b1, nullptr);

    // 9. y2 = yn + h @ ff_w2 + b2
    hgemm256<3,float><<<dim3(C_/256, (B_*N_)/128, 1), 256, SMEM2>>>(ph, pw2T, py2,
        FF_, FF_, FF_, C_, 0L, 0L, 1, 0L, 0L, ff_b2, pyn);

    // 10. LN2 -> out
    ln_part<<<dim3(32, B_), 256>>>(py2);
    ln_fin<<<B_, 32>>>(pstats);
    ln_apply<<<QKV_SZ/256, 256>>>(py2, pstats, ln_g, ln_b, out);
}

// round 7
// speedup vs baseline: 7.0684x; 1.0494x over previous
#include <cuda_runtime.h>
#include <cuda_fp16.h>
#include <math.h>
#include <stdint.h>

// ---------------- problem constants ----------------
#define B_   8
#define N_   256
#define C_   3072
#define H_   8
#define HD_  384
#define FF_  12288
#define P_   32
#define NC_  (N_*C_)
#define BH_  (B_*H_)
#define QKV_SZ   (B_*N_*C_)
#define ATT_SZ   (B_*H_*N_*N_)
#define HBUF_SZ  (B_*N_*FF_)

// ---------------- device scratch ----------------
__device__ __align__(256) __half g_hq[QKV_SZ];
__device__ __align__(256) __half g_hk[QKV_SZ];
__device__ __align__(256) __half g_hvt[QKV_SZ];     // V^T: (BH, hd, N)
__device__ __align__(256) __half g_hattn2[ATT_SZ];
__device__ __align__(256) __half g_hctx[QKV_SZ];
__device__ __align__(256) __half g_hynh[QKV_SZ];
__device__ __align__(256) __half g_hh[HBUF_SZ];
__device__ __align__(256) __half g_hprojT[C_*C_];
__device__ __align__(256) __half g_hw1T[(long)C_*FF_];
__device__ __align__(256) __half g_hw2T[(long)C_*FF_];
__device__ float g_attn[ATT_SZ];
__device__ float g_y1[QKV_SZ];
__device__ float g_yn[QKV_SZ];
__device__ float g_y2[QKV_SZ];
__device__ float g_stats[B_*2];
__device__ double g_part[B_*32*2];

// ---------------- helpers ----------------
__device__ __forceinline__ float gelu_exact(float x) {
    return 0.5f * x * (1.0f + erff(x * 0.70710678118654752f));
}
__device__ __forceinline__ uint32_t smem_u32(const void* p) {
    return (uint32_t)__cvta_generic_to_shared(p);
}
__device__ __forceinline__ void cpa16(uint32_t dst, const void* src) {
    asm volatile("cp.async.cg.shared.global [%0], [%1], 16;\n" :: "r"(dst), "l"(src));
}
__device__ __forceinline__ void cp_commit() { asm volatile("cp.async.commit_group;\n"); }
template<int NN> __device__ __forceinline__ void cp_wait() {
    asm volatile("cp.async.wait_group %0;\n" :: "n"(NN));
}
__device__ __forceinline__ void ldsm_x4(uint32_t* r, uint32_t addr) {
    asm volatile("ldmatrix.sync.aligned.m8n8.x4.shared.b16 {%0,%1,%2,%3}, [%4];"
                 : "=r"(r[0]), "=r"(r[1]), "=r"(r[2]), "=r"(r[3]) : "r"(addr));
}
__device__ __forceinline__ void mma_f16(float c[4], uint32_t a0, uint32_t a1, uint32_t a2,
                                        uint32_t a3, uint32_t b0, uint32_t b1) {
    asm volatile(
        "mma.sync.aligned.m16n8k16.row.col.f32.f16.f16.f32 "
        "{%0,%1,%2,%3},{%4,%5,%6,%7},{%8,%9},{%0,%1,%2,%3};\n"
        : "+f"(c[0]), "+f"(c[1]), "+f"(c[2]), "+f"(c[3])
        : "r"(a0), "r"(a1), "r"(a2), "r"(a3), "r"(b0), "r"(b1));
}

// ================= 128x128 fp16 GEMM (attention AV) =================
#define ASZ  (128*72*2)
#define STG  (2*ASZ)
#define HSMEM (2*STG)

template<int EPI, typename OutT>
__global__ void __launch_bounds__(256, 2)
hgemm(const __half* __restrict__ A, const __half* __restrict__ Bm, OutT* __restrict__ C,
      int K, int lda, int ldb, int ldc,
      long sA, long sB, int zdiv, long sC1, long sC2,
      const float* __restrict__ bias, const float* __restrict__ resid)
{
    extern __shared__ char smem[];
    const uint32_t sbase = smem_u32(smem);

    int tid = threadIdx.x;
    int warp = tid >> 5, lane = tid & 31;
    int wm = warp >> 2, wn = warp & 3;
    int z = blockIdx.z;
    const __half* Ab = A + (long)z * sA;
    const __half* Bb = Bm + (long)z * sB;
    long coff = (long)(z / zdiv) * sC1 + (long)(z % zdiv) * sC2;
    OutT* Cb = C + coff;
    int rowBlk = blockIdx.y * 128;
    int colBlk = blockIdx.x * 128;

    float acc[4][4][4];
    #pragma unroll
    for (int mi = 0; mi < 4; mi++)
        #pragma unroll
        for (int ni = 0; ni < 4; ni++)
            #pragma unroll
            for (int r = 0; r < 4; r++) acc[mi][ni][r] = 0.0f;

    uint32_t aoff = (uint32_t)(((wm*64 + (lane & 15)) * 72 + ((lane >> 4) << 3)) * 2);
    uint32_t boff0 = (uint32_t)(((wn*32 + (lane & 7) + ((lane >> 4) << 3)) * 72 + (lane & 8)) * 2);
    uint32_t boff1 = boff0 + 16u*144u;

    auto load_chunk = [&](int ck, int s) {
        uint32_t ab = sbase + s*STG;
        uint32_t bb = ab + ASZ;
        const __half* Ag = Ab + (long)rowBlk * lda + ck*64;
        const __half* Bg = Bb + (long)colBlk * ldb + ck*64;
        #pragma unroll
        for (int it = 0; it < 4; it++) {
            int idx = tid + it*256;
            int row = idx >> 3, gq = idx & 7;
            cpa16(ab + row*144 + gq*16, Ag + (long)row*lda + gq*8);
        }
        #pragma unroll
        for (int it = 0; it < 4; it++) {
            int idx = tid + it*256;
            int row = idx >> 3, gq = idx & 7;
            cpa16(bb + row*144 + gq*16, Bg + (long)row*ldb + gq*8);
        }
        cp_commit();
    };

    int nc = K >> 6;
    load_chunk(0, 0);

    for (int c = 0; c < nc; c++) {
        int s = c & 1;
        if (c + 1 < nc) { load_chunk(c + 1, s ^ 1); cp_wait<1>(); }
        else            { cp_wait<0>(); }
        __syncthreads();

        uint32_t As = sbase + s*STG;
        uint32_t Bs = As + ASZ;
        #pragma unroll
        for (int kk = 0; kk < 64; kk += 16) {
            uint32_t a[4][4], b[2][4];
            #pragma unroll
            for (int mi = 0; mi < 4; mi++)
                ldsm_x4(a[mi], As + aoff + mi*2304u + kk*2);
            ldsm_x4(b[0], Bs + boff0 + kk*2);
            ldsm_x4(b[1], Bs + boff1 + kk*2);
            #pragma unroll
            for (int mi = 0; mi < 4; mi++)
                #pragma unroll
                for (int ni = 0; ni < 4; ni++)
                    mma_f16(acc[mi][ni], a[mi][0], a[mi][1], a[mi][2], a[mi][3],
                            b[ni >> 1][(ni & 1)*2], b[ni >> 1][(ni & 1)*2 + 1]);
        }
        __syncthreads();
    }

    int g = lane >> 2, t4 = lane & 3;
    #pragma unroll
    for (int mi = 0; mi < 4; mi++) {
        #pragma unroll
        for (int ni = 0; ni < 4; ni++) {
            int r0 = rowBlk + wm*64 + mi*16 + g;
            int c0 = colBlk + wn*32 + ni*8 + 2*t4;
            float v0 = acc[mi][ni][0], v1 = acc[mi][ni][1];
            float v2 = acc[mi][ni][2], v3 = acc[mi][ni][3];
            if (EPI == 0 || EPI == 2) {
                *(__half2*)&((__half*)Cb)[(long)r0*ldc + c0]     = __floats2half2_rn(v0, v1);
                *(__half2*)&((__half*)Cb)[(long)(r0+8)*ldc + c0] = __floats2half2_rn(v2, v3);
            } else {
                *(float2*)&((float*)Cb)[(long)r0*ldc + c0]     = make_float2(v0, v1);
                *(float2*)&((float*)Cb)[(long)(r0+8)*ldc + c0] = make_float2(v2, v3);
            }
        }
    }
}

// ================= 128x256 fp16 GEMM, 512 threads, 4-stage =================
#define A2SZ (128*144)
#define B2SZ (256*144)
#define STG2 (A2SZ + B2SZ)    // 55296
#define SMEM2 (4*STG2)        // 221184

template<int EPI, typename OutT>
__global__ void __launch_bounds__(512, 1)
hgemm256(const __half* __restrict__ A, const __half* __restrict__ Bm, OutT* __restrict__ C,
         int K, int lda, int ldb, int ldc,
         long sA, long sB, int zdiv, long sC1, long sC2,
         const float* __restrict__ bias, const float* __restrict__ resid)
{
    extern __shared__ char smem[];
    const uint32_t sbase = smem_u32(smem);

    int tid = threadIdx.x;
    int warp = tid >> 5, lane = tid & 31;
    int wm = warp >> 2, wn = warp & 3;     // 4x4 warp grid, 32x64 warp tile
    int z = blockIdx.z;
    const __half* Ab = A + (long)z * sA;
    const __half* Bb = Bm + (long)z * sB;
    long coff = (long)(z / zdiv) * sC1 + (long)(z % zdiv) * sC2;
    OutT* Cb = C + coff;
    int rowBlk = blockIdx.y * 128;
    int colBlk = blockIdx.x * 256;

    float acc[2][8][4];
    #pragma unroll
    for (int mi = 0; mi < 2; mi++)
        #pragma unroll
        for (int ni = 0; ni < 8; ni++)
            #pragma unroll
            for (int r = 0; r < 4; r++) acc[mi][ni][r] = 0.0f;

    uint32_t aoff = (uint32_t)(((wm*32 + (lane & 15)) * 72 + ((lane >> 4) << 3)) * 2);
    uint32_t boff = (uint32_t)(((wn*64 + (lane & 7) + ((lane >> 4) << 3)) * 72 + (lane & 8)) * 2);

    auto load_chunk = [&](int ck, int s) {
        uint32_t ab = sbase + s*STG2;
        uint32_t bb = ab + A2SZ;
        const __half* Ag = Ab + (long)rowBlk * lda + ck*64;
        const __half* Bg = Bb + (long)colBlk * ldb + ck*64;
        #pragma unroll
        for (int it = 0; it < 2; it++) {
            int idx = tid + it*512;
            int row = idx >> 3, gq = idx & 7;
            cpa16(ab + row*144 + gq*16, Ag + (long)row*lda + gq*8);
        }
        #pragma unroll
        for (int it = 0; it < 4; it++) {
            int idx = tid + it*512;
            int row = idx >> 3, gq = idx & 7;
            cpa16(bb + row*144 + gq*16, Bg + (long)row*ldb + gq*8);
        }
        cp_commit();
    };

    int nc = K >> 6;
    load_chunk(0, 0);
    if (nc > 1) load_chunk(1, 1); else cp_commit();
    if (nc > 2) load_chunk(2, 2); else cp_commit();

    for (int c = 0; c < nc; c++) {
        cp_wait<2>();
        __syncthreads();
        if (c + 3 < nc) load_chunk(c + 3, (c + 3) & 3);
        else            cp_commit();

        uint32_t As = sbase + (c & 3)*STG2;
        uint32_t Bs = As + A2SZ;

        uint32_t af[2][2][4], bf[2][4][4];
        #pragma unroll
        for (int mi = 0; mi < 2; mi++) ldsm_x4(af[0][mi], As + aoff + mi*2304u);
        #pragma unroll
        for (int j = 0; j < 4; j++)    ldsm_x4(bf[0][j],  Bs + boff + j*2304u);

        #pragma unroll
        for (int ki = 0; ki < 4; ki++) {
            int cur = ki & 1;
            if (ki < 3) {
                int kk2 = (ki + 1) * 16 * 2;
                #pragma unroll
                for (int mi = 0; mi < 2; mi++) ldsm_x4(af[cur^1][mi], As + aoff + mi*2304u + kk2);
                #pragma unroll
                for (int j = 0; j < 4; j++)    ldsm_x4(bf[cur^1][j],  Bs + boff + j*2304u + kk2);
            }
            #pragma unroll
            for (int mi = 0; mi < 2; mi++)
                #pragma unroll
                for (int ni = 0; ni < 8; ni++)
                    mma_f16(acc[mi][ni], af[cur][mi][0], af[cur][mi][1],
                            af[cur][mi][2], af[cur][mi][3],
                            bf[cur][ni >> 1][(ni & 1)*2], bf[cur][ni >> 1][(ni & 1)*2 + 1]);
        }
    }

    __syncthreads();
    int g = lane >> 2, t4 = lane & 3;
    #pragma unroll
    for (int mi = 0; mi < 2; mi++) {
        #pragma unroll
        for (int ni = 0; ni < 8; ni++) {
            int r0 = rowBlk + wm*32 + mi*16 + g;
            int c0 = colBlk + wn*64 + ni*8 + 2*t4;
            float v0 = acc[mi][ni][0], v1 = acc[mi][ni][1];
            float v2 = acc[mi][ni][2], v3 = acc[mi][ni][3];
            if (EPI >= 2) {
                float b0 = bias[c0], b1 = bias[c0+1];
                v0 += b0; v1 += b1; v2 += b0; v3 += b1;
            }
            if (EPI == 2) {
                v0 = gelu_exact(v0); v1 = gelu_exact(v1);
                v2 = gelu_exact(v2); v3 = gelu_exact(v3);
            }
            if (EPI == 3) {
                const float2 ra = *(const float2*)&resid[coff + (long)r0*ldc + c0];
                const float2 rb = *(const float2*)&resid[coff + (long)(r0+8)*ldc + c0];
                v0 += ra.x; v1 += ra.y; v2 += rb.x; v3 += rb.y;
            }
            if (EPI == 0 || EPI == 2) {
                *(__half2*)&((__half*)Cb)[(long)r0*ldc + c0]     = __floats2half2_rn(v0, v1);
                *(__half2*)&((__half*)Cb)[(long)(r0+8)*ldc + c0] = __floats2half2_rn(v2, v3);
            } else {
                *(float2*)&((float*)Cb)[(long)r0*ldc + c0]     = make_float2(v0, v1);
                *(float2*)&((float*)Cb)[(long)(r0+8)*ldc + c0] = make_float2(v2, v3);
            }
        }
    }
}

// ---------------- transpose fp32 -> fp16 ----------------
__global__ void transpose_h(const float* __restrict__ src, __half* __restrict__ dst,
                            int R, int Ccol)
{
    __shared__ float t[32][33];
    int c0 = blockIdx.x * 32, r0 = blockIdx.y * 32;
    int x = c0 + threadIdx.x;
    #pragma unroll
    for (int j = threadIdx.y; j < 32; j += 8)
        t[j][threadIdx.x] = src[(long)(r0 + j) * Ccol + x];
    __syncthreads();
    int x2 = r0 + threadIdx.x;
    #pragma unroll
    for (int j = threadIdx.y; j < 32; j += 8)
        dst[(long)(c0 + j) * R + x2] = __float2half_rn(t[threadIdx.x][j]);
}

// ---------------- fused conv QKV, 4-position register blocking ----------------
__global__ void __launch_bounds__(256, 2) conv_qkv(const float* __restrict__ x,
                                                   const float* __restrict__ qw,
                                                   const float* __restrict__ kw,
                                                   const float* __restrict__ vw)
{
    __shared__ float sp[3][P_+2][P_+2];
    __shared__ float swq[81], swk[81], swv[81];
    int tid = threadIdx.x;
    int patch = blockIdx.x;
    int b = patch >> 8;
    int n = patch & 255;
    const float* xp = x + (long)patch * C_;

    if (tid < 81) { swq[tid] = qw[tid]; swk[tid] = kw[tid]; swv[tid] = vw[tid]; }
    for (int i = tid; i < 3*(P_+2)*(P_+2); i += 256)
        ((float*)sp)[i] = 0.0f;
    __syncthreads();
    for (int i = tid; i < C_; i += 256) {
        int ch = i >> 10;
        int s  = i & 1023;
        sp[ch][(s >> 5)+1][(s & 31)+1] = xp[i];
    }
    __syncthreads();

    int pos0 = tid * 4;
    int yy = pos0 >> 5, xx = pos0 & 31;
    float aq[3][4], ak[3][4], av[3][4];
    #pragma unroll
    for (int o = 0; o < 3; o++)
        #pragma unroll
        for (int p = 0; p < 4; p++) { aq[o][p] = 0.f; ak[o][p] = 0.f; av[o][p] = 0.f; }

    #pragma unroll
    for (int i = 0; i < 3; i++) {
        #pragma unroll
        for (int dy = 0; dy < 3; dy++) {
            float r[6];
            #pragma unroll
            for (int t = 0; t < 6; t++) r[t] = sp[i][yy+dy][xx+t];
            #pragma unroll
            for (int dx = 0; dx < 3; dx++) {
                int wi = i*9 + dy*3 + dx;
                float wq0 = swq[wi], wq1 = swq[27+wi], wq2 = swq[54+wi];
                float wk0 = swk[wi], wk1 = swk[27+wi], wk2 = swk[54+wi];
                float wv0 = swv[wi], wv1 = swv[27+wi], wv2 = swv[54+wi];
                #pragma unroll
                for (int p = 0; p < 4; p++) {
                    float val = r[dx + p];
                    aq[0][p] = fmaf(val, wq0, aq[0][p]);
                    aq[1][p] = fmaf(val, wq1, aq[1][p]);
                    aq[2][p] = fmaf(val, wq2, aq[2][p]);
                    ak[0][p] = fmaf(val, wk0, ak[0][p]);
                    ak[1][p] = fmaf(val, wk1, ak[1][p]);
                    ak[2][p] = fmaf(val, wk2, ak[2][p]);
                    av[0][p] = fmaf(val, wv0, av[0][p]);
                    av[1][p] = fmaf(val, wv1, av[1][p]);
                    av[2][p] = fmaf(val, wv2, av[2][p]);
                }
            }
        }
    }

    #pragma unroll
    for (int o = 0; o < 3; o++) {
        int c0 = o*1024 + pos0;            // multiple of 4, block of 4 stays in one head
        int h = c0 / HD_;
        int d = c0 - h*HD_;
        long bh = (long)(b*H_ + h);
        long base = (bh*N_ + n)*HD_ + d;
        *(__half2*)&g_hq[base]   = __floats2half2_rn(aq[o][0], aq[o][1]);
        *(__half2*)&g_hq[base+2] = __floats2half2_rn(aq[o][2], aq[o][3]);
        *(__half2*)&g_hk[base]   = __floats2half2_rn(ak[o][0], ak[o][1]);
        *(__half2*)&g_hk[base+2] = __floats2half2_rn(ak[o][2], ak[o][3]);
        #pragma unroll
        for (int p = 0; p < 4; p++)
            g_hvt[(bh*HD_ + d + p)*N_ + n] = __float2half_rn(av[o][p]);
    }
}

// ---------------- fused softmax + re-attention + BN -> fp16 ----------------
__global__ void __launch_bounds__(256) softmax_reatten(
    const float* __restrict__ attn, __half* __restrict__ attn2,
    const float* __restrict__ w,  const float* __restrict__ rb,
    const float* __restrict__ g,  const float* __restrict__ bta,
    const float* __restrict__ mean, const float* __restrict__ var)
{
    __shared__ float sp[8][256];
    __shared__ float sw[64], sscale[8], sshift[8];
    int tid = threadIdx.x;
    int h = tid >> 5, lane = tid & 31;
    if (tid < 64) sw[tid] = w[tid];
    if (tid < 8) {
        float inv = rsqrtf(var[tid] + 1e-5f);
        float gi = g[tid] * inv;
        sscale[tid] = gi;
        sshift[tid] = bta[tid] + (rb[tid] - mean[tid]) * gi;
    }
    int b = blockIdx.x >> 8, n = blockIdx.x & 255;
    const float scale = 0.051031036307982884f;
    const float* row = attn + (((long)(b*H_ + h))*N_ + n)*N_;

    float v[8];
    #pragma unroll
    for (int j = 0; j < 8; j++) v[j] = row[lane + j*32] * scale;
    float m = v[0];
    #pragma unroll
    for (int j = 1; j < 8; j++) m = fmaxf(m, v[j]);
    #pragma unroll
    for (int o = 16; o > 0; o >>= 1) m = fmaxf(m, __shfl_xor_sync(0xffffffffu, m, o));
    float s = 0.0f;
    float e[8];
    #pragma unroll
    for (int j = 0; j < 8; j++) { e[j] = __expf(v[j] - m); s += e[j]; }
    #pragma unroll
    for (int o = 16; o > 0; o >>= 1) s += __shfl_xor_sync(0xffffffffu, s, o);
    float inv = 1.0f / s;
    #pragma unroll
    for (int j = 0; j < 8; j++) sp[h][lane + j*32] = e[j] * inv;
    __syncthreads();

    float in[8];
    #pragma unroll
    for (int i = 0; i < 8; i++) in[i] = sp[i][tid];
    #pragma unroll
    for (int o = 0; o < 8; o++) {
        float acc = 0.0f;
        #pragma unroll
        for (int i = 0; i < 8; i++) acc = fmaf(sw[o*8 + i], in[i], acc);
        attn2[(((long)(b*H_ + o))*N_ + n)*N_ + tid] =
            __float2half_rn(acc * sscale[o] + sshift[o]);
    }
}

// ---------------- LayerNorm: two-level stats ----------------
__global__ void ln_part(const float* __restrict__ y)
{
    __shared__ double rs[8], rq[8];
    int b = blockIdx.y, seg = blockIdx.x;
    const float* p = y + (long)b * NC_ + (long)seg * (NC_/32);
    double s = 0.0, q = 0.0;
    for (int i = threadIdx.x; i < NC_/32; i += 256) {
        double v = (double)p[i];
        s += v; q += v * v;
    }
    #pragma unroll
    for (int o = 16; o > 0; o >>= 1) {
        s += __shfl_xor_sync(0xffffffffu, s, o);
        q += __shfl_xor_sync(0xffffffffu, q, o);
    }
    int lane = threadIdx.x & 31, wid = threadIdx.x >> 5;
    if (lane == 0) { rs[wid] = s; rq[wid] = q; }
    __syncthreads();
    if (threadIdx.x == 0) {
        double S = 0.0, Q = 0.0;
        #pragma unroll
        for (int i = 0; i < 8; i++) { S += rs[i]; Q += rq[i]; }
        g_part[(b*32 + seg)*2]     = S;
        g_part[(b*32 + seg)*2 + 1] = Q;
    }
}

__global__ void ln_fin(float* __restrict__ stats)
{
    int b = blockIdx.x, t = threadIdx.x;
    double s = g_part[(b*32 + t)*2];
    double q = g_part[(b*32 + t)*2 + 1];
    #pragma unroll
    for (int o = 16; o > 0; o >>= 1) {
        s += __shfl_xor_sync(0xffffffffu, s, o);
        q += __shfl_xor_sync(0xffffffffu, q, o);
    }
    if (t == 0) {
        double mu  = s / (double)NC_;
        double var = q / (double)NC_ - mu * mu;
        stats[b*2]   = (float)mu;
        stats[b*2+1] = (float)rsqrt(var + 1e-5);
    }
}

__global__ void ln_apply_dual(const float* __restrict__ y, const float* __restrict__ stats,
                              const float* __restrict__ g, const float* __restrict__ beta,
                              float* __restrict__ outf, __half* __restrict__ outh)
{
    long i = (long)blockIdx.x * blockDim.x + threadIdx.x;
    int b = (int)(i / NC_);
    int r = (int)(i % NC_);
    float v = (y[i] - stats[b*2]) * stats[b*2+1] * g[r] + beta[r];
    outf[i] = v;
    outh[i] = __float2half_rn(v);
}

__global__ void ln_apply(const float* __restrict__ y, const float* __restrict__ stats,
                         const float* __restrict__ g, const float* __restrict__ beta,
                         float* __restrict__ out)
{
    long i = (long)blockIdx.x * blockDim.x + threadIdx.x;
    int b = (int)(i / NC_);
    int r = (int)(i % NC_);
    out[i] = (y[i] - stats[b*2]) * stats[b*2+1] * g[r] + beta[r];
}

// ---------------- launch ----------------
extern "C" void kernel_launch(void* const* d_in, const int* in_sizes, int n_in,
                              void* d_out, int out_size)
{
    const float* x        = (const float*)d_in[0];
    const float* qconv_w  = (const float*)d_in[1];
    const float* kconv_w  = (const float*)d_in[2];
    const float* vconv_w  = (const float*)d_in[3];
    const float* reat_w   = (const float*)d_in[4];
    const float* reat_b   = (const float*)d_in[5];
    const float* bn_gamma = (const float*)d_in[6];
    const float* bn_beta  = (const float*)d_in[7];
    const float* bn_mean  = (const float*)d_in[8];
    const float* bn_var   = (const float*)d_in[9];
    const float* proj_w   = (const float*)d_in[10];
    const float* proj_b   = (const float*)d_in[11];
    const float* ln_g     = (const float*)d_in[12];
    const float* ln_b     = (const float*)d_in[13];
    const float* ff_w1    = (const float*)d_in[14];
    const float* ff_b1    = (const float*)d_in[15];
    const float* ff_w2    = (const float*)d_in[16];
    const float* ff_b2    = (const float*)d_in[17];
    float* out = (float*)d_out;

    __half *pq, *pk, *pvt, *pattn2, *pctx, *pynh, *ph, *pprojT, *pw1T, *pw2T;
    float *pattn, *py1, *pyn, *py2, *pstats;
    cudaGetSymbolAddress((void**)&pq,     g_hq);
    cudaGetSymbolAddress((void**)&pk,     g_hk);
    cudaGetSymbolAddress((void**)&pvt,    g_hvt);
    cudaGetSymbolAddress((void**)&pattn2, g_hattn2);
    cudaGetSymbolAddress((void**)&pctx,   g_hctx);
    cudaGetSymbolAddress((void**)&pynh,   g_hynh);
    cudaGetSymbolAddress((void**)&ph,     g_hh);
    cudaGetSymbolAddress((void**)&pprojT, g_hprojT);
    cudaGetSymbolAddress((void**)&pw1T,   g_hw1T);
    cudaGetSymbolAddress((void**)&pw2T,   g_hw2T);
    cudaGetSymbolAddress((void**)&pattn,  g_attn);
    cudaGetSymbolAddress((void**)&py1,    g_y1);
    cudaGetSymbolAddress((void**)&pyn,    g_yn);
    cudaGetSymbolAddress((void**)&py2,    g_y2);
    cudaGetSymbolAddress((void**)&pstats, g_stats);

    cudaFuncSetAttribute(hgemm<0,__half>,    cudaFuncAttributeMaxDynamicSharedMemorySize, HSMEM);
    cudaFuncSetAttribute(hgemm256<1,float>,  cudaFuncAttributeMaxDynamicSharedMemorySize, SMEM2);
    cudaFuncSetAttribute(hgemm256<2,__half>, cudaFuncAttributeMaxDynamicSharedMemorySize, SMEM2);
    cudaFuncSetAttribute(hgemm256<3,float>,  cudaFuncAttributeMaxDynamicSharedMemorySize, SMEM2);

    // 1. fused conv QKV  (launch index 0)
    conv_qkv<<<B_*N_, 256>>>(x, qconv_w, kconv_w, vconv_w);

    // 2. S = Q K^T  (launch 1)
    hgemm256<1,float><<<dim3(1,2,BH_), 512, SMEM2>>>(pq, pk, pattn,
        HD_, HD_, HD_, N_, (long)N_*HD_, (long)N_*HD_, 1, 65536L, 0L, nullptr, nullptr);

    // 3. fused softmax + re-attention (launch 2)
    softmax_reatten<<<B_*N_, 256>>>(pattn, pattn2, reat_w, reat_b,
                                    bn_gamma, bn_beta, bn_mean, bn_var);

    // 4. ctx = attn2 @ V (launch 3)
    hgemm<0,__half><<<dim3(3,2,BH_), 256, HSMEM>>>(pattn2, pvt, pctx,
        N_, N_, N_, C_, 65536L, (long)HD_*N_, H_, (long)N_*C_, (long)HD_, nullptr, nullptr);

    // 5. proj weight transpose (launch 4)
    {
        dim3 blk(32, 8);
        transpose_h<<<dim3(C_/32, C_/32), blk>>>(proj_w, pprojT, C_, C_);
    }

    // 6. y1 = x + ctx @ proj_w + proj_b  (launch 5 — ncu target)
    hgemm256<3,float><<<dim3(C_/256, (B_*N_)/128, 1), 512, SMEM2>>>(pctx, pprojT, py1,
        C_, C_, C_, C_, 0L, 0L, 1, 0L, 0L, proj_b, x);

    // 7. FFN weight transposes
    {
        dim3 blk(32, 8);
        transpose_h<<<dim3(FF_/32, C_/32), blk>>>(ff_w1, pw1T, C_, FF_);
        transpose_h<<<dim3(C_/32, FF_/32), blk>>>(ff_w2, pw2T, FF_, C_);
    }

    // 8. LN1
    ln_part<<<dim3(32, B_), 256>>>(py1);
    ln_fin<<<B_, 32>>>(pstats);
    ln_apply_dual<<<QKV_SZ/256, 256>>>(py1, pstats, ln_g, ln_b, pyn, pynh);

    // 9. h = gelu(yn @ ff_w1 + b1)
    hgemm256<2,__half><<<dim3(FF_/256, (B_*N_)/128, 1), 512, SMEM2>>>(pynh, pw1T, ph,
        C_, C_, C_, FF_, 0L, 0L, 1, 0L, 0L, ff_b1, nullptr);

    // 10. y2 = yn + h @ ff_w2 + b2
    hgemm256<3,float><<<dim3(C_/256, (B_*N_)/128, 1), 512, SMEM2>>>(ph, pw2T, py2,
        FF_, FF_, FF_, C_, 0L, 0L, 1, 0L, 0L, ff_b2, pyn);

    // 11. LN2 -> out
    ln_part<<<dim3(32, B_), 256>>>(py2);
    ln_fin<<<B_, 32>>>(pstats);
    ln_apply<<<QKV_SZ/256, 256>>>(py2, pstats, ln_g, ln_b, out);
}